// round 12
// baseline (speedup 1.0000x reference)
#include <cuda_runtime.h>
#include <cuda_bf16.h>
#include <math.h>
#include <stdint.h>

#define Bsz  16
#define Cdim 64
#define Lseq 1024
#define Hn   8
#define HC   512
#define NH   128   // B*H batch-heads

// ---------------- scratch (static device memory; no allocations) ----------------
__device__ float g_PW[1536 * 64];
__device__ float g_WF[1536 * 15];
__device__ __nv_bfloat16 g_Q[NH * Lseq * Cdim];   // (n, l, c) bf16, pre-scaled x0.125
__device__ __nv_bfloat16 g_K[NH * Lseq * Cdim];   // (n, l, c) bf16
__device__ __nv_bfloat16 g_V[NH * Cdim * Lseq];   // (n, c, l) bf16
__device__ __nv_bfloat16 g_ATT[Bsz * Lseq * HC];  // (b, l, hc) bf16
__device__ float g_Y[Bsz * Cdim * Lseq];          // LN1 out fp32 (b, c, l)
__device__ __nv_bfloat16 g_Yh[Bsz * Lseq * Cdim]; // LN1 out bf16 (b, l, c)
__device__ __nv_bfloat16 g_H[Bsz * Lseq * 256];   // FFN hidden bf16 (b, l, 256)
__device__ __nv_bfloat16 g_Wu[64 * 512];          // bf16 weights
__device__ __nv_bfloat16 g_W1[256 * 64];
__device__ __nv_bfloat16 g_W2[64 * 256];

__device__ __forceinline__ uint32_t bfpack(float lo, float hi) {
    __nv_bfloat162 h = __floats2bfloat162_rn(lo, hi);
    return *reinterpret_cast<uint32_t*>(&h);
}
__device__ __forceinline__ uint32_t smem_u32(const void* p) {
    uint32_t a;
    asm("{ .reg .u64 t; cvta.to.shared.u64 t, %1; cvt.u32.u64 %0, t; }" : "=r"(a) : "l"(p));
    return a;
}
__device__ __forceinline__ void mma_bf16(float* c, const uint32_t* a, uint32_t b0, uint32_t b1) {
    asm volatile(
        "mma.sync.aligned.m16n8k16.row.col.f32.bf16.bf16.f32 "
        "{%0,%1,%2,%3}, {%4,%5,%6,%7}, {%8,%9}, {%0,%1,%2,%3};"
        : "+f"(c[0]), "+f"(c[1]), "+f"(c[2]), "+f"(c[3])
        : "r"(a[0]), "r"(a[1]), "r"(a[2]), "r"(a[3]), "r"(b0), "r"(b1));
}
__device__ __forceinline__ void ldsm4(uint32_t& r0, uint32_t& r1, uint32_t& r2, uint32_t& r3,
                                      uint32_t addr) {
    asm volatile("ldmatrix.sync.aligned.m8n8.x4.shared.b16 {%0,%1,%2,%3}, [%4];"
                 : "=r"(r0), "=r"(r1), "=r"(r2), "=r"(r3) : "r"(addr));
}
#define CP16(dst, src) \
    asm volatile("cp.async.cg.shared.global [%0], [%1], 16;" :: "r"(dst), "l"(src))
#define CP_COMMIT() asm volatile("cp.async.commit_group;" ::: "memory")
#define CP_WAIT1()  asm volatile("cp.async.wait_group 1;" ::: "memory")

// ---------------- K0: fold gate softmax into combined conv weights ----------------
__global__ void combine_kernel(
    const float* __restrict__ pw0, const float* __restrict__ gt0,
    const float* __restrict__ d3_0, const float* __restrict__ d15_0,
    const float* __restrict__ pw1, const float* __restrict__ gt1,
    const float* __restrict__ d3_1, const float* __restrict__ d15_1,
    const float* __restrict__ pw2, const float* __restrict__ gt2,
    const float* __restrict__ d3_2, const float* __restrict__ d15_2,
    float* __restrict__ PW, float* __restrict__ WF)
{
    int o = blockIdx.x * 256 + threadIdx.x;
    if (o >= 1536) return;
    int s = o >> 9, lc = o & 511;
    const float *pw, *gt, *d3, *d15;
    if (s == 0)      { pw = pw0; gt = gt0; d3 = d3_0; d15 = d15_0; }
    else if (s == 1) { pw = pw1; gt = gt1; d3 = d3_1; d15 = d15_1; }
    else             { pw = pw2; gt = gt2; d3 = d3_2; d15 = d15_2; }
    float a = gt[0], b = gt[1];
    float mx = fmaxf(a, b);
    float e0 = expf(a - mx), e1 = expf(b - mx);
    float inv = 1.0f / (e0 + e1);
    float ga = e0 * inv, gb = e1 * inv;
    for (int c = 0; c < 64; c++) PW[(size_t)o * 64 + c] = pw[(size_t)lc * 64 + c];
    for (int t = 0; t < 15; t++) {
        float w = gb * d15[lc * 15 + t];
        if (t >= 6 && t < 9) w += ga * d3[lc * 3 + (t - 6)];
        WF[o * 15 + t] = w;
    }
}

// ---------------- K0b: convert GEMM weights to bf16 ----------------
__global__ void convw_kernel(const float* __restrict__ wu, const float* __restrict__ w1,
                             const float* __restrict__ w2)
{
    int i = blockIdx.x * 256 + threadIdx.x;
    if (i < 32768)       g_Wu[i] = __float2bfloat16_rn(wu[i]);
    else if (i < 49152)  g_W1[i - 32768] = __float2bfloat16_rn(w1[i - 32768]);
    else if (i < 65536)  g_W2[i - 49152] = __float2bfloat16_rn(w2[i - 49152]);
}

// ---------------- K1: fused pointwise GEMM + depthwise conv15 -> Q/K/V (bf16 out) ----------------
__global__ __launch_bounds__(256) void qkv_kernel(
    const float* __restrict__ q,
    const float* __restrict__ PW, const float* __restrict__ WF,
    __nv_bfloat16* __restrict__ Qp, __nv_bfloat16* __restrict__ Kp,
    __nv_bfloat16* __restrict__ Vp)
{
    extern __shared__ float sm1[];
    float* xs  = sm1;               // [64][144]
    float* mid = xs + 64 * 144;     // [32][144]
    float* spw = mid + 32 * 144;    // [32][64]
    float* swf = spw + 32 * 64;     // [32][16]
    int tid = threadIdx.x;
    int l0 = blockIdx.x * 128;
    int o0 = blockIdx.y * 32;
    int b  = blockIdx.z;

    for (int e = tid; e < 64 * 144; e += 256) {
        int c = e / 144, j = e - c * 144;
        int gl = l0 - 7 + j;
        float v = 0.f;
        if (gl >= 0 && gl < Lseq) v = q[((size_t)b * 64 + c) * Lseq + gl];
        xs[c * 144 + j] = v;
    }
    for (int e = tid; e < 32 * 64; e += 256) spw[e] = PW[(size_t)o0 * 64 + e];
    for (int e = tid; e < 32 * 15; e += 256) {
        int o = e / 15, t = e - o * 15;
        swf[o * 16 + t] = WF[(size_t)(o0 + o) * 15 + t];
    }
    __syncthreads();

    for (int e = tid; e < 32 * 36; e += 256) {
        int o = e / 36, jq = e - o * 36;
        const float* pwrow = spw + o * 64;
        const float* xcol  = xs + jq * 4;
        float4 acc = make_float4(0.f, 0.f, 0.f, 0.f);
#pragma unroll 8
        for (int c = 0; c < 64; c++) {
            float w = pwrow[c];
            float4 xv = *(const float4*)(xcol + c * 144);
            acc.x += w * xv.x; acc.y += w * xv.y; acc.z += w * xv.z; acc.w += w * xv.w;
        }
        *(float4*)(mid + o * 144 + jq * 4) = acc;
    }
    __syncthreads();

    int s = o0 >> 9;
    float scale = (s == 0) ? 0.125f : 1.0f;
    for (int e = tid; e < 32 * 128; e += 256) {
        int o = e >> 7, i = e & 127;
        const float* mrow = mid + o * 144;
        const float* wrow = swf + o * 16;
        float acc = 0.f;
#pragma unroll
        for (int t = 0; t < 15; t++) acc += wrow[t] * mrow[i + t];
        acc *= scale;
        int og = o0 + o;
        int ch = og & 511;
        int head = ch >> 6, c = ch & 63;
        size_t n = (size_t)b * 8 + head;
        __nv_bfloat16 hv = __float2bfloat16_rn(acc);
        if (s == 2) {
            Vp[(n * 64 + c) * Lseq + l0 + i] = hv;                  // (n, c, l)
        } else {
            __nv_bfloat16* base = (s == 0) ? Qp : Kp;
            base[(n * Lseq + l0 + i) * 64 + c] = hv;                // (n, l, c)
        }
    }
}

// ---------------- K2: flash attention (unchanged core; bf16 (b,l,hc) output) ----------------
#define KVS 72
#define BUFE (64 * KVS)
__global__ __launch_bounds__(256, 2) void attn_bf16(
    const __nv_bfloat16* __restrict__ Qt, const __nv_bfloat16* __restrict__ Kt,
    const __nv_bfloat16* __restrict__ Vg, __nv_bfloat16* __restrict__ att)
{
    __shared__ __nv_bfloat16 Ks[2][BUFE];
    __shared__ __nv_bfloat16 Vs[2][BUFE];
    int tid = threadIdx.x, w = tid >> 5, lane = tid & 31;
    int g = lane >> 2, r = lane & 3;
    int n = blockIdx.y, q0 = blockIdx.x * 128;

    const __nv_bfloat16* Qb = Qt + (size_t)n * (Lseq * 64) + (size_t)(q0 + w * 16) * 64;
    const __nv_bfloat16* Kb = Kt + (size_t)n * (Lseq * 64);
    const __nv_bfloat16* Vb = Vg + (size_t)n * (64 * Lseq);

    int kr0 = tid >> 3, kg0 = tid & 7;
    int kr1 = (tid + 256) >> 3, kg1 = (tid + 256) & 7;
    uint32_t ks_base = smem_u32(&Ks[0][0]);
    uint32_t vs_base = smem_u32(&Vs[0][0]);
    uint32_t kd0 = ks_base + (kr0 * KVS + kg0 * 8) * 2;
    uint32_t kd1 = ks_base + (kr1 * KVS + kg1 * 8) * 2;
    uint32_t vd0 = vs_base + (kr0 * KVS + kg0 * 8) * 2;
    uint32_t vd1 = vs_base + (kr1 * KVS + kg1 * 8) * 2;

    int sel = lane >> 3, lrow = lane & 7;
    int mrow = ((sel >> 1) << 3) + lrow;
    int mcol = (sel & 1) << 3;
    uint32_t kls = ks_base + (mrow * KVS + mcol) * 2;
    uint32_t vls = vs_base + (mrow * KVS + mcol) * 2;

    uint32_t qf[16];
#pragma unroll
    for (int kc = 0; kc < 4; kc++) {
        qf[kc * 4 + 0] = *(const uint32_t*)(Qb + (size_t)g * 64 + kc * 16 + 2 * r);
        qf[kc * 4 + 1] = *(const uint32_t*)(Qb + (size_t)(g + 8) * 64 + kc * 16 + 2 * r);
        qf[kc * 4 + 2] = *(const uint32_t*)(Qb + (size_t)g * 64 + kc * 16 + 2 * r + 8);
        qf[kc * 4 + 3] = *(const uint32_t*)(Qb + (size_t)(g + 8) * 64 + kc * 16 + 2 * r + 8);
    }

#pragma unroll
    for (int t = 0; t < 2; t++) {
        int k0 = t * 64;
        uint32_t bo = t * BUFE * 2;
        CP16(kd0 + bo, Kb + (size_t)(k0 + kr0) * 64 + kg0 * 8);
        CP16(kd1 + bo, Kb + (size_t)(k0 + kr1) * 64 + kg1 * 8);
        CP16(vd0 + bo, Vb + (size_t)kr0 * Lseq + k0 + kg0 * 8);
        CP16(vd1 + bo, Vb + (size_t)kr1 * Lseq + k0 + kg1 * 8);
        CP_COMMIT();
    }

    float oacc[32];
#pragma unroll
    for (int i = 0; i < 32; i++) oacc[i] = 0.f;
    float m0 = -INFINITY, m1 = -INFINITY, l0 = 0.f, l1 = 0.f;

    for (int kt = 0; kt < 16; kt++) {
        CP_WAIT1();
        __syncthreads();
        uint32_t bo = (kt & 1) * BUFE * 2;

        float sacc[32];
#pragma unroll
        for (int i = 0; i < 32; i++) sacc[i] = 0.f;
#pragma unroll
        for (int kc = 0; kc < 4; kc++) {
#pragma unroll
            for (int nb2 = 0; nb2 < 4; nb2++) {
                uint32_t b0, b1, b2, b3;
                ldsm4(b0, b1, b2, b3, kls + bo + nb2 * (16 * KVS * 2) + kc * 32);
                mma_bf16(sacc + (2 * nb2) * 4,     qf + kc * 4, b0, b1);
                mma_bf16(sacc + (2 * nb2 + 1) * 4, qf + kc * 4, b2, b3);
            }
        }

        float tm0 = -INFINITY, tm1 = -INFINITY;
#pragma unroll
        for (int nb = 0; nb < 8; nb++) {
            tm0 = fmaxf(tm0, fmaxf(sacc[nb * 4 + 0], sacc[nb * 4 + 1]));
            tm1 = fmaxf(tm1, fmaxf(sacc[nb * 4 + 2], sacc[nb * 4 + 3]));
        }
        tm0 = fmaxf(tm0, __shfl_xor_sync(0xffffffffu, tm0, 1));
        tm0 = fmaxf(tm0, __shfl_xor_sync(0xffffffffu, tm0, 2));
        tm1 = fmaxf(tm1, __shfl_xor_sync(0xffffffffu, tm1, 1));
        tm1 = fmaxf(tm1, __shfl_xor_sync(0xffffffffu, tm1, 2));
        float mn0 = fmaxf(m0, tm0), mn1 = fmaxf(m1, tm1);
        float al0 = __expf(m0 - mn0), al1 = __expf(m1 - mn1);
        m0 = mn0; m1 = mn1;
        float s0 = 0.f, s1 = 0.f;
        uint32_t plo[8], phi[8];
#pragma unroll
        for (int nb = 0; nb < 8; nb++) {
            float p0 = __expf(sacc[nb * 4 + 0] - mn0);
            float p1 = __expf(sacc[nb * 4 + 1] - mn0);
            float p2 = __expf(sacc[nb * 4 + 2] - mn1);
            float p3 = __expf(sacc[nb * 4 + 3] - mn1);
            s0 += p0 + p1; s1 += p2 + p3;
            plo[nb] = bfpack(p0, p1);
            phi[nb] = bfpack(p2, p3);
        }
        s0 += __shfl_xor_sync(0xffffffffu, s0, 1);
        s0 += __shfl_xor_sync(0xffffffffu, s0, 2);
        s1 += __shfl_xor_sync(0xffffffffu, s1, 1);
        s1 += __shfl_xor_sync(0xffffffffu, s1, 2);
        l0 = l0 * al0 + s0;
        l1 = l1 * al1 + s1;
#pragma unroll
        for (int nb = 0; nb < 8; nb++) {
            oacc[nb * 4 + 0] *= al0; oacc[nb * 4 + 1] *= al0;
            oacc[nb * 4 + 2] *= al1; oacc[nb * 4 + 3] *= al1;
        }

#pragma unroll
        for (int kc = 0; kc < 4; kc++) {
            uint32_t pa[4] = {plo[2 * kc], phi[2 * kc], plo[2 * kc + 1], phi[2 * kc + 1]};
#pragma unroll
            for (int nb2 = 0; nb2 < 4; nb2++) {
                uint32_t b0, b1, b2, b3;
                ldsm4(b0, b1, b2, b3, vls + bo + nb2 * (16 * KVS * 2) + kc * 32);
                mma_bf16(oacc + (2 * nb2) * 4,     pa, b0, b1);
                mma_bf16(oacc + (2 * nb2 + 1) * 4, pa, b2, b3);
            }
        }

        __syncthreads();
        if (kt < 14) {
            int k0 = (kt + 2) * 64;
            uint32_t nb_ = (kt & 1) * BUFE * 2;
            CP16(kd0 + nb_, Kb + (size_t)(k0 + kr0) * 64 + kg0 * 8);
            CP16(kd1 + nb_, Kb + (size_t)(k0 + kr1) * 64 + kg1 * 8);
            CP16(vd0 + nb_, Vb + (size_t)kr0 * Lseq + k0 + kg0 * 8);
            CP16(vd1 + nb_, Vb + (size_t)kr1 * Lseq + k0 + kg1 * 8);
        }
        CP_COMMIT();
    }

    // epilogue: O / l -> att (b, l, head*64+c) bf16
    float inv0 = 1.0f / l0, inv1 = 1.0f / l1;
    int bb = n >> 3, head = n & 7;
    int qg0 = q0 + w * 16 + g, qg1 = qg0 + 8;
#pragma unroll
    for (int nb = 0; nb < 8; nb++) {
        int c = head * 64 + nb * 8 + 2 * r;
        *(uint32_t*)&att[((size_t)bb * Lseq + qg0) * 512 + c] =
            bfpack(oacc[nb * 4 + 0] * inv0, oacc[nb * 4 + 1] * inv0);
        *(uint32_t*)&att[((size_t)bb * Lseq + qg1) * 512 + c] =
            bfpack(oacc[nb * 4 + 2] * inv1, oacc[nb * 4 + 3] * inv1);
    }
}

// ---------------- K3/K5: bf16 mma GEMM (64 x Kdim) + bias + residual + channel LN ----------------
// grid (16 Ltiles of 64, 16 b); 256 threads; warp = (wm 0-3 m-block, wn 0-1 l-half)
__global__ __launch_bounds__(256) void gemm_ln_kernel(
    const __nv_bfloat16* __restrict__ X,   // (b, 1024, Kdim) bf16
    const __nv_bfloat16* __restrict__ Wg,  // (64, Kdim) bf16
    const float* __restrict__ bias, const float* __restrict__ res,  // res (b,64,1024) f32
    const float* __restrict__ gam, const float* __restrict__ bet,
    float* __restrict__ outF,              // (b,64,1024) f32
    __nv_bfloat16* __restrict__ outH,      // (b,1024,64) bf16 or nullptr
    int Kdim)
{
    __shared__ __align__(16) char SM[36864];
    __shared__ float ps1[4 * 64], ps2[4 * 64], mu_s[64], iv_s[64];
    __shared__ float gs[64], bts[64], bss[64];
    int tid = threadIdx.x, w = tid >> 5, lane = tid & 31;
    int wm = w >> 1, wn = w & 1;
    int g = lane >> 2, r = lane & 3;
    int l0 = blockIdx.x * 64;
    int b  = blockIdx.y;
    int nch = Kdim >> 6;

    if (tid < 64) { gs[tid] = gam[tid]; bts[tid] = bet[tid]; bss[tid] = bias[tid]; }

    uint32_t asb = smem_u32(SM);
    uint32_t bsb = asb + 18432;
    uint32_t a_off = (uint32_t)(((wm * 16 + (lane & 15)) * KVS + ((lane >> 4) << 3)) * 2);
    uint32_t b_off = (uint32_t)(((wn * 32 + (((lane >> 4) & 1) << 3) + (lane & 7)) * KVS +
                                 (((lane >> 3) & 1) << 3)) * 2);
    int sr0 = tid >> 3, sg0 = tid & 7;           // staging row/granule (2 per thread)
    int sr1 = (tid + 256) >> 3, sg1 = (tid + 256) & 7;
    uint32_t ad0 = asb + (sr0 * KVS + sg0 * 8) * 2;
    uint32_t ad1 = asb + (sr1 * KVS + sg1 * 8) * 2;
    uint32_t bd0 = bsb + (sr0 * KVS + sg0 * 8) * 2;
    uint32_t bd1 = bsb + (sr1 * KVS + sg1 * 8) * 2;
    const __nv_bfloat16* Xb = X + (size_t)b * Lseq * Kdim;

#pragma unroll
    for (int t = 0; t < 2; t++) {
        int cb = t * 64;
        uint32_t bo = t * 9216;
        CP16(ad0 + bo, Wg + (size_t)sr0 * Kdim + cb + sg0 * 8);
        CP16(ad1 + bo, Wg + (size_t)sr1 * Kdim + cb + sg1 * 8);
        CP16(bd0 + bo, Xb + (size_t)(l0 + sr0) * Kdim + cb + sg0 * 8);
        CP16(bd1 + bo, Xb + (size_t)(l0 + sr1) * Kdim + cb + sg1 * 8);
        CP_COMMIT();
    }

    float acc[16];
#pragma unroll
    for (int i = 0; i < 16; i++) acc[i] = 0.f;

    for (int c = 0; c < nch; c++) {
        CP_WAIT1();
        __syncthreads();
        uint32_t bo = (c & 1) * 9216;
        uint32_t ab = asb + bo + a_off;
        uint32_t bb2 = bsb + bo + b_off;
#pragma unroll
        for (int kc = 0; kc < 4; kc++) {
            uint32_t af0, af1, af2, af3;
            ldsm4(af0, af1, af2, af3, ab + kc * 32);
            uint32_t af[4] = {af0, af1, af2, af3};
            uint32_t b0, b1, b2, b3;
            ldsm4(b0, b1, b2, b3, bb2 + kc * 32);
            mma_bf16(acc + 0, af, b0, b1);
            mma_bf16(acc + 4, af, b2, b3);
            ldsm4(b0, b1, b2, b3, bb2 + 16 * KVS * 2 + kc * 32);
            mma_bf16(acc + 8,  af, b0, b1);
            mma_bf16(acc + 12, af, b2, b3);
        }
        __syncthreads();
        if (c + 2 < nch) {
            int cb = (c + 2) * 64;
            uint32_t nb_ = (c & 1) * 9216;
            CP16(ad0 + nb_, Wg + (size_t)sr0 * Kdim + cb + sg0 * 8);
            CP16(ad1 + nb_, Wg + (size_t)sr1 * Kdim + cb + sg1 * 8);
            CP16(bd0 + nb_, Xb + (size_t)(l0 + sr0) * Kdim + cb + sg0 * 8);
            CP16(bd1 + nb_, Xb + (size_t)(l0 + sr1) * Kdim + cb + sg1 * 8);
        }
        CP_COMMIT();
    }
    __syncthreads();   // done with smem buffers; reuse as T / R

    float* T = (float*)SM;                 // [64][68] accum+bias
    float* R = (float*)(SM + 18432);       // [64][68] residual
    {
        float bv0 = bss[wm * 16 + g], bv1 = bss[wm * 16 + g + 8];
#pragma unroll
        for (int p = 0; p < 2; p++)
#pragma unroll
            for (int blk = 0; blk < 2; blk++) {
                int lb = wn * 32 + p * 16 + blk * 8 + 2 * r;
                int i = (p * 2 + blk) * 4;
                *(float2*)&T[(wm * 16 + g) * 68 + lb]     = make_float2(acc[i] + bv0, acc[i + 1] + bv0);
                *(float2*)&T[(wm * 16 + g + 8) * 68 + lb] = make_float2(acc[i + 2] + bv1, acc[i + 3] + bv1);
            }
    }
    for (int e = tid; e < 1024; e += 256) {
        int row = e >> 4, sg = e & 15;
        *(float4*)&R[row * 68 + sg * 4] =
            *(const float4*)&res[((size_t)b * 64 + row) * Lseq + l0 + sg * 4];
    }
    __syncthreads();

    {
        int l = tid & 63, p = tid >> 6;
        float s1 = 0.f, s2 = 0.f;
#pragma unroll
        for (int ch = p * 16; ch < p * 16 + 16; ch++) {
            float v = T[ch * 68 + l] + R[ch * 68 + l];
            s1 += v; s2 += v * v;
        }
        ps1[p * 64 + l] = s1; ps2[p * 64 + l] = s2;
    }
    __syncthreads();
    if (tid < 64) {
        float s1 = ps1[tid] + ps1[64 + tid] + ps1[128 + tid] + ps1[192 + tid];
        float s2 = ps2[tid] + ps2[64 + tid] + ps2[128 + tid] + ps2[192 + tid];
        float mu = s1 * (1.0f / 64.0f);
        float var = s2 * (1.0f / 64.0f) - mu * mu;
        mu_s[tid] = mu;
        iv_s[tid] = rsqrtf(var + 1e-5f);
    }
    __syncthreads();

    {   // fp32 out (b, c, l)
        int ch = tid >> 2, ls = (tid & 3) * 16;
        float gv = gs[ch], bv = bts[ch];
        float* op = outF + ((size_t)b * 64 + ch) * Lseq + l0 + ls;
#pragma unroll
        for (int j = 0; j < 16; j += 4) {
            float4 ov;
            float* tp = &T[ch * 68 + ls + j];
            float* rp = &R[ch * 68 + ls + j];
            ov.x = (tp[0] + rp[0] - mu_s[ls + j + 0]) * iv_s[ls + j + 0] * gv + bv;
            ov.y = (tp[1] + rp[1] - mu_s[ls + j + 1]) * iv_s[ls + j + 1] * gv + bv;
            ov.z = (tp[2] + rp[2] - mu_s[ls + j + 2]) * iv_s[ls + j + 2] * gv + bv;
            ov.w = (tp[3] + rp[3] - mu_s[ls + j + 3]) * iv_s[ls + j + 3] * gv + bv;
            *(float4*)(op + j) = ov;
        }
    }
    if (outH) {   // bf16 out (b, l, c)
        int l = tid >> 2, cs = (tid & 3) * 16;
        float mu = mu_s[l], iv = iv_s[l];
        __nv_bfloat16* hp = outH + ((size_t)b * Lseq + l0 + l) * 64 + cs;
#pragma unroll
        for (int c = 0; c < 16; c += 2) {
            float v0 = (T[(cs + c) * 68 + l] + R[(cs + c) * 68 + l] - mu) * iv * gs[cs + c] + bts[cs + c];
            float v1 = (T[(cs + c + 1) * 68 + l] + R[(cs + c + 1) * 68 + l] - mu) * iv * gs[cs + c + 1] + bts[cs + c + 1];
            *(uint32_t*)(hp + c) = bfpack(v0, v1);
        }
    }
}

// ---------------- K4: FFN up-projection bf16 mma (64 out-block x K=64) + ReLU ----------------
// grid (16 Ltiles, 4 m-blocks, 16 b)
__global__ __launch_bounds__(256) void ffn1_mma(
    const __nv_bfloat16* __restrict__ X,   // g_Yh (b, 1024, 64)
    const __nv_bfloat16* __restrict__ Wg,  // g_W1 (256, 64)
    const float* __restrict__ bias,
    __nv_bfloat16* __restrict__ H)         // (b, 1024, 256)
{
    __shared__ __align__(16) __nv_bfloat16 As[64 * KVS];
    __shared__ __align__(16) __nv_bfloat16 Bs[64 * KVS];
    __shared__ float T[64 * 68];
    __shared__ float bss[64];
    int tid = threadIdx.x, w = tid >> 5, lane = tid & 31;
    int wm = w >> 1, wn = w & 1;
    int g = lane >> 2, r = lane & 3;
    int l0 = blockIdx.x * 64;
    int mb = blockIdx.y;
    int b  = blockIdx.z;

    if (tid < 64) bss[tid] = bias[mb * 64 + tid];
    for (int e = tid; e < 512; e += 256) {
        int row = e >> 3, kg = e & 7;
        *(uint4*)&As[row * KVS + kg * 8] =
            *(const uint4*)&Wg[(size_t)(mb * 64 + row) * 64 + kg * 8];
        *(uint4*)&Bs[row * KVS + kg * 8] =
            *(const uint4*)&X[((size_t)b * Lseq + l0 + row) * 64 + kg * 8];
    }
    __syncthreads();

    uint32_t ab = smem_u32(As) + (((wm * 16 + (lane & 15)) * KVS + ((lane >> 4) << 3)) * 2);
    uint32_t bb2 = smem_u32(Bs) + (((wn * 32 + (((lane >> 4) & 1) << 3) + (lane & 7)) * KVS +
                                    (((lane >> 3) & 1) << 3)) * 2);
    float acc[16];
#pragma unroll
    for (int i = 0; i < 16; i++) acc[i] = 0.f;
#pragma unroll
    for (int kc = 0; kc < 4; kc++) {
        uint32_t af0, af1, af2, af3;
        ldsm4(af0, af1, af2, af3, ab + kc * 32);
        uint32_t af[4] = {af0, af1, af2, af3};
        uint32_t b0, b1, b2, b3;
        ldsm4(b0, b1, b2, b3, bb2 + kc * 32);
        mma_bf16(acc + 0, af, b0, b1);
        mma_bf16(acc + 4, af, b2, b3);
        ldsm4(b0, b1, b2, b3, bb2 + 16 * KVS * 2 + kc * 32);
        mma_bf16(acc + 8,  af, b0, b1);
        mma_bf16(acc + 12, af, b2, b3);
    }
    __syncthreads();
    {
        float bv0 = bss[wm * 16 + g], bv1 = bss[wm * 16 + g + 8];
#pragma unroll
        for (int p = 0; p < 2; p++)
#pragma unroll
            for (int blk = 0; blk < 2; blk++) {
                int lb = wn * 32 + p * 16 + blk * 8 + 2 * r;
                int i = (p * 2 + blk) * 4;
                *(float2*)&T[(wm * 16 + g) * 68 + lb]     = make_float2(acc[i] + bv0, acc[i + 1] + bv0);
                *(float2*)&T[(wm * 16 + g + 8) * 68 + lb] = make_float2(acc[i + 2] + bv1, acc[i + 3] + bv1);
            }
    }
    __syncthreads();
    {
        int l = tid >> 2, cs = (tid & 3) * 16;
        __nv_bfloat16* hp = H + ((size_t)b * Lseq + l0 + l) * 256 + mb * 64 + cs;
#pragma unroll
        for (int c = 0; c < 16; c += 2) {
            float v0 = fmaxf(T[(cs + c) * 68 + l], 0.f);
            float v1 = fmaxf(T[(cs + c + 1) * 68 + l], 0.f);
            *(uint32_t*)(hp + c) = bfpack(v0, v1);
        }
    }
}

// ---------------- launch ----------------
extern "C" void kernel_launch(void* const* d_in, const int* in_sizes, int n_in,
                              void* d_out, int out_size)
{
    const float* q       = (const float*)d_in[0];
    const float* wq_pw   = (const float*)d_in[1];
    const float* wq_gate = (const float*)d_in[2];
    const float* wq_dw3  = (const float*)d_in[3];
    const float* wq_dw15 = (const float*)d_in[4];
    const float* wk_pw   = (const float*)d_in[5];
    const float* wk_gate = (const float*)d_in[6];
    const float* wk_dw3  = (const float*)d_in[7];
    const float* wk_dw15 = (const float*)d_in[8];
    const float* wv_pw   = (const float*)d_in[9];
    const float* wv_gate = (const float*)d_in[10];
    const float* wv_dw3  = (const float*)d_in[11];
    const float* wv_dw15 = (const float*)d_in[12];
    const float* w_unify = (const float*)d_in[13];
    const float* b_unify = (const float*)d_in[14];
    const float* ln1_g   = (const float*)d_in[15];
    const float* ln1_b   = (const float*)d_in[16];
    const float* ln2_g   = (const float*)d_in[17];
    const float* ln2_b   = (const float*)d_in[18];
    const float* ffn_w1  = (const float*)d_in[19];
    const float* ffn_b1  = (const float*)d_in[20];
    const float* ffn_w2  = (const float*)d_in[21];
    const float* ffn_b2  = (const float*)d_in[22];
    float* out = (float*)d_out;

    void *pPW, *pWF, *pQ, *pK, *pV, *pATT, *pY, *pYh, *pH, *pWu, *pW1, *pW2;
    cudaGetSymbolAddress(&pPW, g_PW);
    cudaGetSymbolAddress(&pWF, g_WF);
    cudaGetSymbolAddress(&pQ, g_Q);
    cudaGetSymbolAddress(&pK, g_K);
    cudaGetSymbolAddress(&pV, g_V);
    cudaGetSymbolAddress(&pATT, g_ATT);
    cudaGetSymbolAddress(&pY, g_Y);
    cudaGetSymbolAddress(&pYh, g_Yh);
    cudaGetSymbolAddress(&pH, g_H);
    cudaGetSymbolAddress(&pWu, g_Wu);
    cudaGetSymbolAddress(&pW1, g_W1);
    cudaGetSymbolAddress(&pW2, g_W2);

    cudaFuncSetAttribute(qkv_kernel, cudaFuncAttributeMaxDynamicSharedMemorySize, 65536);

    combine_kernel<<<6, 256>>>(
        wq_pw, wq_gate, wq_dw3, wq_dw15,
        wk_pw, wk_gate, wk_dw3, wk_dw15,
        wv_pw, wv_gate, wv_dw3, wv_dw15,
        (float*)pPW, (float*)pWF);

    convw_kernel<<<256, 256>>>(w_unify, ffn_w1, ffn_w2);

    qkv_kernel<<<dim3(8, 48, 16), 256, 65536>>>(
        q, (const float*)pPW, (const float*)pWF,
        (__nv_bfloat16*)pQ, (__nv_bfloat16*)pK, (__nv_bfloat16*)pV);

    attn_bf16<<<dim3(8, 128), 256>>>(
        (const __nv_bfloat16*)pQ, (const __nv_bfloat16*)pK,
        (const __nv_bfloat16*)pV, (__nv_bfloat16*)pATT);

    gemm_ln_kernel<<<dim3(16, 16), 256>>>(
        (const __nv_bfloat16*)pATT, (const __nv_bfloat16*)pWu,
        b_unify, q, ln1_g, ln1_b,
        (float*)pY, (__nv_bfloat16*)pYh, 512);

    ffn1_mma<<<dim3(16, 4, 16), 256>>>(
        (const __nv_bfloat16*)pYh, (const __nv_bfloat16*)pW1,
        ffn_b1, (__nv_bfloat16*)pH);

    gemm_ln_kernel<<<dim3(16, 16), 256>>>(
        (const __nv_bfloat16*)pH, (const __nv_bfloat16*)pW2,
        ffn_b2, (const float*)pY, ln2_g, ln2_b,
        out, (__nv_bfloat16*)nullptr, 256);
}

// round 14
// speedup vs baseline: 1.4675x; 1.4675x over previous
#include <cuda_runtime.h>
#include <cuda_fp16.h>
#include <math.h>
#include <stdint.h>

#define Bsz  16
#define Cdim 64
#define Lseq 1024
#define Hn   8
#define HC   512
#define NH   128   // B*H batch-heads

// ---------------- scratch (static device memory; no allocations) ----------------
__device__ float g_PW[1536 * 64];
__device__ float g_WF[1536 * 15];
__device__ __half g_qT[Bsz * Lseq * Cdim];     // input transposed (b, l, c) fp16
__device__ __half g_Q[NH * Lseq * Cdim];       // (n, l, c) fp16, pre-scaled x0.125
__device__ __half g_K[NH * Lseq * Cdim];       // (n, l, c) fp16
__device__ __half g_V[NH * Cdim * Lseq];       // (n, c, l) fp16
__device__ __half g_ATT[Bsz * Lseq * HC];      // (b, l, hc) fp16
__device__ float g_Y[Bsz * Cdim * Lseq];       // LN1 out fp32 (b, c, l)
__device__ __half g_Yh[Bsz * Lseq * Cdim];     // LN1 out fp16 (b, l, c)
__device__ __half g_H[Bsz * Lseq * 256];       // FFN hidden fp16 (b, l, 256)
__device__ __half g_Wu[64 * 512];
__device__ __half g_W1[256 * 64];
__device__ __half g_W2[64 * 256];

__device__ __forceinline__ uint32_t hpack(float lo, float hi) {
    __half2 h = __floats2half2_rn(lo, hi);
    return *reinterpret_cast<uint32_t*>(&h);
}
__device__ __forceinline__ uint32_t smem_u32(const void* p) {
    uint32_t a;
    asm("{ .reg .u64 t; cvta.to.shared.u64 t, %1; cvt.u32.u64 %0, t; }" : "=r"(a) : "l"(p));
    return a;
}
__device__ __forceinline__ void mma_f16(float* c, const uint32_t* a, uint32_t b0, uint32_t b1) {
    asm volatile(
        "mma.sync.aligned.m16n8k16.row.col.f32.f16.f16.f32 "
        "{%0,%1,%2,%3}, {%4,%5,%6,%7}, {%8,%9}, {%0,%1,%2,%3};"
        : "+f"(c[0]), "+f"(c[1]), "+f"(c[2]), "+f"(c[3])
        : "r"(a[0]), "r"(a[1]), "r"(a[2]), "r"(a[3]), "r"(b0), "r"(b1));
}
__device__ __forceinline__ void ldsm4(uint32_t& r0, uint32_t& r1, uint32_t& r2, uint32_t& r3,
                                      uint32_t addr) {
    asm volatile("ldmatrix.sync.aligned.m8n8.x4.shared.b16 {%0,%1,%2,%3}, [%4];"
                 : "=r"(r0), "=r"(r1), "=r"(r2), "=r"(r3) : "r"(addr));
}
#define CP16(dst, src) \
    asm volatile("cp.async.cg.shared.global [%0], [%1], 16;" :: "r"(dst), "l"(src))
#define CP_COMMIT() asm volatile("cp.async.commit_group;" ::: "memory")
#define CP_WAIT1()  asm volatile("cp.async.wait_group 1;" ::: "memory")

// ---------------- K0: fold gate softmax into combined conv weights ----------------
__global__ void combine_kernel(
    const float* __restrict__ pw0, const float* __restrict__ gt0,
    const float* __restrict__ d3_0, const float* __restrict__ d15_0,
    const float* __restrict__ pw1, const float* __restrict__ gt1,
    const float* __restrict__ d3_1, const float* __restrict__ d15_1,
    const float* __restrict__ pw2, const float* __restrict__ gt2,
    const float* __restrict__ d3_2, const float* __restrict__ d15_2,
    float* __restrict__ PW, float* __restrict__ WF)
{
    int o = blockIdx.x * 256 + threadIdx.x;
    if (o >= 1536) return;
    int s = o >> 9, lc = o & 511;
    const float *pw, *gt, *d3, *d15;
    if (s == 0)      { pw = pw0; gt = gt0; d3 = d3_0; d15 = d15_0; }
    else if (s == 1) { pw = pw1; gt = gt1; d3 = d3_1; d15 = d15_1; }
    else             { pw = pw2; gt = gt2; d3 = d3_2; d15 = d15_2; }
    float a = gt[0], b = gt[1];
    float mx = fmaxf(a, b);
    float e0 = expf(a - mx), e1 = expf(b - mx);
    float inv = 1.0f / (e0 + e1);
    float ga = e0 * inv, gb = e1 * inv;
    for (int c = 0; c < 64; c++) PW[(size_t)o * 64 + c] = pw[(size_t)lc * 64 + c];
    for (int t = 0; t < 15; t++) {
        float w = gb * d15[lc * 15 + t];
        if (t >= 6 && t < 9) w += ga * d3[lc * 3 + (t - 6)];
        WF[o * 15 + t] = w;
    }
}

// ---------------- K0b: weights -> fp16 ----------------
__global__ void convw_kernel(const float* __restrict__ wu, const float* __restrict__ w1,
                             const float* __restrict__ w2)
{
    int i = blockIdx.x * 256 + threadIdx.x;
    if (i < 32768)       g_Wu[i] = __float2half_rn(wu[i]);
    else if (i < 49152)  g_W1[i - 32768] = __float2half_rn(w1[i - 32768]);
    else if (i < 65536)  g_W2[i - 49152] = __float2half_rn(w2[i - 49152]);
}

// ---------------- K0c: transpose q (b,c,l) f32 -> (b,l,c) fp16 ----------------
__global__ __launch_bounds__(256) void transpose_kernel(
    const float* __restrict__ q, __half* __restrict__ qT)
{
    __shared__ float tile[64][33];
    int b = blockIdx.y, l0 = blockIdx.x * 32;
    int t = threadIdx.x;
    int c = t >> 2, lo4 = (t & 3) * 8;
    float4 v0 = *(const float4*)&q[((size_t)b * 64 + c) * Lseq + l0 + lo4];
    float4 v1 = *(const float4*)&q[((size_t)b * 64 + c) * Lseq + l0 + lo4 + 4];
    // scalar stores: 33-stride rows are NOT 16B-aligned for odd c
    tile[c][lo4 + 0] = v0.x; tile[c][lo4 + 1] = v0.y;
    tile[c][lo4 + 2] = v0.z; tile[c][lo4 + 3] = v0.w;
    tile[c][lo4 + 4] = v1.x; tile[c][lo4 + 5] = v1.y;
    tile[c][lo4 + 6] = v1.z; tile[c][lo4 + 7] = v1.w;
    __syncthreads();
    int l = t >> 3, c0 = (t & 7) * 8;
    uint32_t hp[4];
#pragma unroll
    for (int j = 0; j < 4; j++)
        hp[j] = hpack(tile[c0 + 2 * j][l], tile[c0 + 2 * j + 1][l]);
    *(uint4*)&qT[((size_t)b * Lseq + l0 + l) * 64 + c0] = *(uint4*)hp;
}

// ---------------- K1: qkv via fp16 mma pointwise + fp32 depthwise conv ----------------
// grid (8 Ltiles of 128, 24 o-blocks of 64, 16 b); 256 threads. dyn smem 40960.
#define BST 72          // fp16 row stride in staging tiles
__global__ __launch_bounds__(256) void qkv_mma(
    const __half* __restrict__ qT,
    const float* __restrict__ PW, const float* __restrict__ WF,
    __half* __restrict__ Qp, __half* __restrict__ Kp, __half* __restrict__ Vp)
{
    extern __shared__ __align__(16) char SM[];
    __half* As = (__half*)SM;               // [64][72]
    __half* Bs = (__half*)(SM + 9216);      // [160][72]
    float*  mid = (float*)SM;               // [64][160] (reused after mma)
    __shared__ float swf[64 * 16];
    int tid = threadIdx.x, w = tid >> 5, lane = tid & 31;
    int wm = w >> 1, wn = w & 1;
    int g = lane >> 2, r = lane & 3;
    int l0 = blockIdx.x * 128;
    int o0 = blockIdx.y * 64;
    int b  = blockIdx.z;

    // stage A (weights fp32 -> fp16), conv weights
    for (int e = tid; e < 4096; e += 256) {
        int o = e >> 6, c = e & 63;
        As[o * BST + c] = __float2half_rn(PW[(size_t)(o0 + o) * 64 + c]);
    }
    for (int e = tid; e < 64 * 15; e += 256) {
        int o = e / 15, t = e - o * 15;
        swf[o * 16 + t] = WF[(size_t)(o0 + o) * 15 + t];
    }
    // stage B: rows j=0..159 <-> position l0-7+j (zero pad OOB / j>=144)
    const __half* qTb = qT + (size_t)b * Lseq * 64;
#pragma unroll
    for (int k = 0; k < 5; k++) {
        int gi = tid + k * 256;
        int row = gi >> 3, gr = gi & 7;
        int l = l0 - 7 + row;
        uint4 v = make_uint4(0, 0, 0, 0);
        if (row < 144 && l >= 0 && l < Lseq)
            v = *(const uint4*)&qTb[(size_t)l * 64 + gr * 8];
        *(uint4*)&Bs[row * BST + gr * 8] = v;
    }
    __syncthreads();

    uint32_t asb = smem_u32(As), bsb = smem_u32(Bs);
    uint32_t a_off = asb + (((wm * 16 + (lane & 15)) * BST + ((lane >> 4) << 3)) * 2);
    uint32_t b_off = bsb + (((wn * 80 + (((lane >> 4) & 1) << 3) + (lane & 7)) * BST +
                             (((lane >> 3) & 1) << 3)) * 2);
    float acc[40];
#pragma unroll
    for (int i = 0; i < 40; i++) acc[i] = 0.f;
#pragma unroll
    for (int kc = 0; kc < 4; kc++) {
        uint32_t af0, af1, af2, af3;
        ldsm4(af0, af1, af2, af3, a_off + kc * 32);
        uint32_t af[4] = {af0, af1, af2, af3};
#pragma unroll
        for (int nb2 = 0; nb2 < 5; nb2++) {
            uint32_t b0, b1, b2, b3;
            ldsm4(b0, b1, b2, b3, b_off + nb2 * (16 * BST * 2) + kc * 32);
            mma_f16(acc + (nb2 * 2 + 0) * 4, af, b0, b1);
            mma_f16(acc + (nb2 * 2 + 1) * 4, af, b2, b3);
        }
    }
    __syncthreads();   // staging dead; write mid

    {
        int ro0 = wm * 16 + g, ro1 = ro0 + 8;
#pragma unroll
        for (int nb2 = 0; nb2 < 5; nb2++)
#pragma unroll
            for (int blk = 0; blk < 2; blk++) {
                int col = wn * 80 + nb2 * 16 + blk * 8 + 2 * r;
                int i = (nb2 * 2 + blk) * 4;
                *(float2*)&mid[ro0 * 160 + col] = make_float2(acc[i], acc[i + 1]);
                *(float2*)&mid[ro1 * 160 + col] = make_float2(acc[i + 2], acc[i + 3]);
            }
    }
    __syncthreads();

    // depthwise conv15 + scatter (block covers exactly one head's 64 channels)
    int s = o0 >> 9;
    float scale = (s == 0) ? 0.125f : 1.0f;
    int ch = o0 & 511, head = ch >> 6;
    size_t n = (size_t)b * 8 + head;
    for (int e = tid; e < 64 * 128; e += 256) {
        int o = e >> 7, i = e & 127;
        const float* mrow = mid + o * 160;
        const float* wrow = swf + o * 16;
        float acc2 = 0.f;
#pragma unroll
        for (int t = 0; t < 15; t++) acc2 += wrow[t] * mrow[i + t];
        __half hv = __float2half_rn(acc2 * scale);
        if (s == 2) {
            Vp[(n * 64 + o) * Lseq + l0 + i] = hv;              // (n, c, l)
        } else {
            __half* base = (s == 0) ? Qp : Kp;
            base[(n * Lseq + l0 + i) * 64 + o] = hv;            // (n, l, c)
        }
    }
}

// ---------------- K2: flash attention fp16 ----------------
#define KVS 72
#define BUFE (64 * KVS)
__global__ __launch_bounds__(256, 2) void attn_f16(
    const __half* __restrict__ Qt, const __half* __restrict__ Kt,
    const __half* __restrict__ Vg, __half* __restrict__ att)
{
    __shared__ __half Ks[2][BUFE];
    __shared__ __half Vs[2][BUFE];
    int tid = threadIdx.x, w = tid >> 5, lane = tid & 31;
    int g = lane >> 2, r = lane & 3;
    int n = blockIdx.y, q0 = blockIdx.x * 128;

    const __half* Qb = Qt + (size_t)n * (Lseq * 64) + (size_t)(q0 + w * 16) * 64;
    const __half* Kb = Kt + (size_t)n * (Lseq * 64);
    const __half* Vb = Vg + (size_t)n * (64 * Lseq);

    int kr0 = tid >> 3, kg0 = tid & 7;
    int kr1 = (tid + 256) >> 3, kg1 = (tid + 256) & 7;
    uint32_t ks_base = smem_u32(&Ks[0][0]);
    uint32_t vs_base = smem_u32(&Vs[0][0]);
    uint32_t kd0 = ks_base + (kr0 * KVS + kg0 * 8) * 2;
    uint32_t kd1 = ks_base + (kr1 * KVS + kg1 * 8) * 2;
    uint32_t vd0 = vs_base + (kr0 * KVS + kg0 * 8) * 2;
    uint32_t vd1 = vs_base + (kr1 * KVS + kg1 * 8) * 2;

    int sel = lane >> 3, lrow = lane & 7;
    int mrow = ((sel >> 1) << 3) + lrow;
    int mcol = (sel & 1) << 3;
    uint32_t kls = ks_base + (mrow * KVS + mcol) * 2;
    uint32_t vls = vs_base + (mrow * KVS + mcol) * 2;

    uint32_t qf[16];
#pragma unroll
    for (int kc = 0; kc < 4; kc++) {
        qf[kc * 4 + 0] = *(const uint32_t*)(Qb + (size_t)g * 64 + kc * 16 + 2 * r);
        qf[kc * 4 + 1] = *(const uint32_t*)(Qb + (size_t)(g + 8) * 64 + kc * 16 + 2 * r);
        qf[kc * 4 + 2] = *(const uint32_t*)(Qb + (size_t)g * 64 + kc * 16 + 2 * r + 8);
        qf[kc * 4 + 3] = *(const uint32_t*)(Qb + (size_t)(g + 8) * 64 + kc * 16 + 2 * r + 8);
    }

#pragma unroll
    for (int t = 0; t < 2; t++) {
        int k0 = t * 64;
        uint32_t bo = t * BUFE * 2;
        CP16(kd0 + bo, Kb + (size_t)(k0 + kr0) * 64 + kg0 * 8);
        CP16(kd1 + bo, Kb + (size_t)(k0 + kr1) * 64 + kg1 * 8);
        CP16(vd0 + bo, Vb + (size_t)kr0 * Lseq + k0 + kg0 * 8);
        CP16(vd1 + bo, Vb + (size_t)kr1 * Lseq + k0 + kg1 * 8);
        CP_COMMIT();
    }

    float oacc[32];
#pragma unroll
    for (int i = 0; i < 32; i++) oacc[i] = 0.f;
    float m0 = -INFINITY, m1 = -INFINITY, l0 = 0.f, l1 = 0.f;

    for (int kt = 0; kt < 16; kt++) {
        CP_WAIT1();
        __syncthreads();
        uint32_t bo = (kt & 1) * BUFE * 2;

        float sacc[32];
#pragma unroll
        for (int i = 0; i < 32; i++) sacc[i] = 0.f;
#pragma unroll
        for (int kc = 0; kc < 4; kc++) {
#pragma unroll
            for (int nb2 = 0; nb2 < 4; nb2++) {
                uint32_t b0, b1, b2, b3;
                ldsm4(b0, b1, b2, b3, kls + bo + nb2 * (16 * KVS * 2) + kc * 32);
                mma_f16(sacc + (2 * nb2) * 4,     qf + kc * 4, b0, b1);
                mma_f16(sacc + (2 * nb2 + 1) * 4, qf + kc * 4, b2, b3);
            }
        }

        float tm0 = -INFINITY, tm1 = -INFINITY;
#pragma unroll
        for (int nb = 0; nb < 8; nb++) {
            tm0 = fmaxf(tm0, fmaxf(sacc[nb * 4 + 0], sacc[nb * 4 + 1]));
            tm1 = fmaxf(tm1, fmaxf(sacc[nb * 4 + 2], sacc[nb * 4 + 3]));
        }
        tm0 = fmaxf(tm0, __shfl_xor_sync(0xffffffffu, tm0, 1));
        tm0 = fmaxf(tm0, __shfl_xor_sync(0xffffffffu, tm0, 2));
        tm1 = fmaxf(tm1, __shfl_xor_sync(0xffffffffu, tm1, 1));
        tm1 = fmaxf(tm1, __shfl_xor_sync(0xffffffffu, tm1, 2));
        float mn0 = fmaxf(m0, tm0), mn1 = fmaxf(m1, tm1);
        float al0 = __expf(m0 - mn0), al1 = __expf(m1 - mn1);
        m0 = mn0; m1 = mn1;
        float s0 = 0.f, s1 = 0.f;
        uint32_t plo[8], phi[8];
#pragma unroll
        for (int nb = 0; nb < 8; nb++) {
            float p0 = __expf(sacc[nb * 4 + 0] - mn0);
            float p1 = __expf(sacc[nb * 4 + 1] - mn0);
            float p2 = __expf(sacc[nb * 4 + 2] - mn1);
            float p3 = __expf(sacc[nb * 4 + 3] - mn1);
            s0 += p0 + p1; s1 += p2 + p3;
            plo[nb] = hpack(p0, p1);
            phi[nb] = hpack(p2, p3);
        }
        s0 += __shfl_xor_sync(0xffffffffu, s0, 1);
        s0 += __shfl_xor_sync(0xffffffffu, s0, 2);
        s1 += __shfl_xor_sync(0xffffffffu, s1, 1);
        s1 += __shfl_xor_sync(0xffffffffu, s1, 2);
        l0 = l0 * al0 + s0;
        l1 = l1 * al1 + s1;
#pragma unroll
        for (int nb = 0; nb < 8; nb++) {
            oacc[nb * 4 + 0] *= al0; oacc[nb * 4 + 1] *= al0;
            oacc[nb * 4 + 2] *= al1; oacc[nb * 4 + 3] *= al1;
        }

#pragma unroll
        for (int kc = 0; kc < 4; kc++) {
            uint32_t pa[4] = {plo[2 * kc], phi[2 * kc], plo[2 * kc + 1], phi[2 * kc + 1]};
#pragma unroll
            for (int nb2 = 0; nb2 < 4; nb2++) {
                uint32_t b0, b1, b2, b3;
                ldsm4(b0, b1, b2, b3, vls + bo + nb2 * (16 * KVS * 2) + kc * 32);
                mma_f16(oacc + (2 * nb2) * 4,     pa, b0, b1);
                mma_f16(oacc + (2 * nb2 + 1) * 4, pa, b2, b3);
            }
        }

        __syncthreads();
        if (kt < 14) {
            int k0 = (kt + 2) * 64;
            uint32_t nb_ = (kt & 1) * BUFE * 2;
            CP16(kd0 + nb_, Kb + (size_t)(k0 + kr0) * 64 + kg0 * 8);
            CP16(kd1 + nb_, Kb + (size_t)(k0 + kr1) * 64 + kg1 * 8);
            CP16(vd0 + nb_, Vb + (size_t)kr0 * Lseq + k0 + kg0 * 8);
            CP16(vd1 + nb_, Vb + (size_t)kr1 * Lseq + k0 + kg1 * 8);
        }
        CP_COMMIT();
    }

    float inv0 = 1.0f / l0, inv1 = 1.0f / l1;
    int bb = n >> 3, head = n & 7;
    int qg0 = q0 + w * 16 + g, qg1 = qg0 + 8;
#pragma unroll
    for (int nb = 0; nb < 8; nb++) {
        int c = head * 64 + nb * 8 + 2 * r;
        *(uint32_t*)&att[((size_t)bb * Lseq + qg0) * 512 + c] =
            hpack(oacc[nb * 4 + 0] * inv0, oacc[nb * 4 + 1] * inv0);
        *(uint32_t*)&att[((size_t)bb * Lseq + qg1) * 512 + c] =
            hpack(oacc[nb * 4 + 2] * inv1, oacc[nb * 4 + 3] * inv1);
    }
}

// ---------------- K3/K5: fp16 mma GEMM (64 x Kdim) + bias + residual + channel LN ----------------
__global__ __launch_bounds__(256) void gemm_ln_kernel(
    const __half* __restrict__ X,    // (b, 1024, Kdim) fp16
    const __half* __restrict__ Wg,   // (64, Kdim) fp16
    const float* __restrict__ bias, const float* __restrict__ res,
    const float* __restrict__ gam, const float* __restrict__ bet,
    float* __restrict__ outF,
    __half* __restrict__ outH,
    int Kdim)
{
    __shared__ __align__(16) char SM[36864];
    __shared__ float ps1[4 * 64], ps2[4 * 64], mu_s[64], iv_s[64];
    __shared__ float gs[64], bts[64], bss[64];
    int tid = threadIdx.x, w = tid >> 5, lane = tid & 31;
    int wm = w >> 1, wn = w & 1;
    int g = lane >> 2, r = lane & 3;
    int l0 = blockIdx.x * 64;
    int b  = blockIdx.y;
    int nch = Kdim >> 6;

    if (tid < 64) { gs[tid] = gam[tid]; bts[tid] = bet[tid]; bss[tid] = bias[tid]; }

    uint32_t asb = smem_u32(SM);
    uint32_t bsb = asb + 18432;
    uint32_t a_off = (uint32_t)(((wm * 16 + (lane & 15)) * KVS + ((lane >> 4) << 3)) * 2);
    uint32_t b_off = (uint32_t)(((wn * 32 + (((lane >> 4) & 1) << 3) + (lane & 7)) * KVS +
                                 (((lane >> 3) & 1) << 3)) * 2);
    int sr0 = tid >> 3, sg0 = tid & 7;
    int sr1 = (tid + 256) >> 3, sg1 = (tid + 256) & 7;
    uint32_t ad0 = asb + (sr0 * KVS + sg0 * 8) * 2;
    uint32_t ad1 = asb + (sr1 * KVS + sg1 * 8) * 2;
    uint32_t bd0 = bsb + (sr0 * KVS + sg0 * 8) * 2;
    uint32_t bd1 = bsb + (sr1 * KVS + sg1 * 8) * 2;
    const __half* Xb = X + (size_t)b * Lseq * Kdim;

#pragma unroll
    for (int t = 0; t < 2; t++) {
        int cb = t * 64;
        uint32_t bo = t * 9216;
        CP16(ad0 + bo, Wg + (size_t)sr0 * Kdim + cb + sg0 * 8);
        CP16(ad1 + bo, Wg + (size_t)sr1 * Kdim + cb + sg1 * 8);
        CP16(bd0 + bo, Xb + (size_t)(l0 + sr0) * Kdim + cb + sg0 * 8);
        CP16(bd1 + bo, Xb + (size_t)(l0 + sr1) * Kdim + cb + sg1 * 8);
        CP_COMMIT();
    }

    float acc[16];
#pragma unroll
    for (int i = 0; i < 16; i++) acc[i] = 0.f;

    for (int c = 0; c < nch; c++) {
        CP_WAIT1();
        __syncthreads();
        uint32_t bo = (c & 1) * 9216;
        uint32_t ab = asb + bo + a_off;
        uint32_t bb2 = bsb + bo + b_off;
#pragma unroll
        for (int kc = 0; kc < 4; kc++) {
            uint32_t af0, af1, af2, af3;
            ldsm4(af0, af1, af2, af3, ab + kc * 32);
            uint32_t af[4] = {af0, af1, af2, af3};
            uint32_t b0, b1, b2, b3;
            ldsm4(b0, b1, b2, b3, bb2 + kc * 32);
            mma_f16(acc + 0, af, b0, b1);
            mma_f16(acc + 4, af, b2, b3);
            ldsm4(b0, b1, b2, b3, bb2 + 16 * KVS * 2 + kc * 32);
            mma_f16(acc + 8,  af, b0, b1);
            mma_f16(acc + 12, af, b2, b3);
        }
        __syncthreads();
        if (c + 2 < nch) {
            int cb = (c + 2) * 64;
            uint32_t nb_ = (c & 1) * 9216;
            CP16(ad0 + nb_, Wg + (size_t)sr0 * Kdim + cb + sg0 * 8);
            CP16(ad1 + nb_, Wg + (size_t)sr1 * Kdim + cb + sg1 * 8);
            CP16(bd0 + nb_, Xb + (size_t)(l0 + sr0) * Kdim + cb + sg0 * 8);
            CP16(bd1 + nb_, Xb + (size_t)(l0 + sr1) * Kdim + cb + sg1 * 8);
        }
        CP_COMMIT();
    }
    __syncthreads();

    float* T = (float*)SM;
    float* R = (float*)(SM + 18432);
    {
        float bv0 = bss[wm * 16 + g], bv1 = bss[wm * 16 + g + 8];
#pragma unroll
        for (int p = 0; p < 2; p++)
#pragma unroll
            for (int blk = 0; blk < 2; blk++) {
                int lb = wn * 32 + p * 16 + blk * 8 + 2 * r;
                int i = (p * 2 + blk) * 4;
                *(float2*)&T[(wm * 16 + g) * 68 + lb]     = make_float2(acc[i] + bv0, acc[i + 1] + bv0);
                *(float2*)&T[(wm * 16 + g + 8) * 68 + lb] = make_float2(acc[i + 2] + bv1, acc[i + 3] + bv1);
            }
    }
    for (int e = tid; e < 1024; e += 256) {
        int row = e >> 4, sg = e & 15;
        *(float4*)&R[row * 68 + sg * 4] =
            *(const float4*)&res[((size_t)b * 64 + row) * Lseq + l0 + sg * 4];
    }
    __syncthreads();

    {
        int l = tid & 63, p = tid >> 6;
        float s1 = 0.f, s2 = 0.f;
#pragma unroll
        for (int ch = p * 16; ch < p * 16 + 16; ch++) {
            float v = T[ch * 68 + l] + R[ch * 68 + l];
            s1 += v; s2 += v * v;
        }
        ps1[p * 64 + l] = s1; ps2[p * 64 + l] = s2;
    }
    __syncthreads();
    if (tid < 64) {
        float s1 = ps1[tid] + ps1[64 + tid] + ps1[128 + tid] + ps1[192 + tid];
        float s2 = ps2[tid] + ps2[64 + tid] + ps2[128 + tid] + ps2[192 + tid];
        float mu = s1 * (1.0f / 64.0f);
        float var = s2 * (1.0f / 64.0f) - mu * mu;
        mu_s[tid] = mu;
        iv_s[tid] = rsqrtf(var + 1e-5f);
    }
    __syncthreads();

    {
        int ch = tid >> 2, ls = (tid & 3) * 16;
        float gv = gs[ch], bv = bts[ch];
        float* op = outF + ((size_t)b * 64 + ch) * Lseq + l0 + ls;
#pragma unroll
        for (int j = 0; j < 16; j += 4) {
            float4 ov;
            float* tp = &T[ch * 68 + ls + j];
            float* rp = &R[ch * 68 + ls + j];
            ov.x = (tp[0] + rp[0] - mu_s[ls + j + 0]) * iv_s[ls + j + 0] * gv + bv;
            ov.y = (tp[1] + rp[1] - mu_s[ls + j + 1]) * iv_s[ls + j + 1] * gv + bv;
            ov.z = (tp[2] + rp[2] - mu_s[ls + j + 2]) * iv_s[ls + j + 2] * gv + bv;
            ov.w = (tp[3] + rp[3] - mu_s[ls + j + 3]) * iv_s[ls + j + 3] * gv + bv;
            *(float4*)(op + j) = ov;
        }
    }
    if (outH) {
        int l = tid >> 2, cs = (tid & 3) * 16;
        float mu = mu_s[l], iv = iv_s[l];
        __half* hp = outH + ((size_t)b * Lseq + l0 + l) * 64 + cs;
#pragma unroll
        for (int c = 0; c < 16; c += 2) {
            float v0 = (T[(cs + c) * 68 + l] + R[(cs + c) * 68 + l] - mu) * iv * gs[cs + c] + bts[cs + c];
            float v1 = (T[(cs + c + 1) * 68 + l] + R[(cs + c + 1) * 68 + l] - mu) * iv * gs[cs + c + 1] + bts[cs + c + 1];
            *(uint32_t*)(hp + c) = hpack(v0, v1);
        }
    }
}

// ---------------- K4: FFN up-projection fp16 mma + ReLU ----------------
__global__ __launch_bounds__(256) void ffn1_mma(
    const __half* __restrict__ X, const __half* __restrict__ Wg,
    const float* __restrict__ bias, __half* __restrict__ H)
{
    __shared__ __align__(16) __half As[64 * KVS];
    __shared__ __align__(16) __half Bs[64 * KVS];
    __shared__ float T[64 * 68];
    __shared__ float bss[64];
    int tid = threadIdx.x, w = tid >> 5, lane = tid & 31;
    int wm = w >> 1, wn = w & 1;
    int g = lane >> 2, r = lane & 3;
    int l0 = blockIdx.x * 64;
    int mb = blockIdx.y;
    int b  = blockIdx.z;

    if (tid < 64) bss[tid] = bias[mb * 64 + tid];
    for (int e = tid; e < 512; e += 256) {
        int row = e >> 3, kg = e & 7;
        *(uint4*)&As[row * KVS + kg * 8] =
            *(const uint4*)&Wg[(size_t)(mb * 64 + row) * 64 + kg * 8];
        *(uint4*)&Bs[row * KVS + kg * 8] =
            *(const uint4*)&X[((size_t)b * Lseq + l0 + row) * 64 + kg * 8];
    }
    __syncthreads();

    uint32_t ab = smem_u32(As) + (((wm * 16 + (lane & 15)) * KVS + ((lane >> 4) << 3)) * 2);
    uint32_t bb2 = smem_u32(Bs) + (((wn * 32 + (((lane >> 4) & 1) << 3) + (lane & 7)) * KVS +
                                    (((lane >> 3) & 1) << 3)) * 2);
    float acc[16];
#pragma unroll
    for (int i = 0; i < 16; i++) acc[i] = 0.f;
#pragma unroll
    for (int kc = 0; kc < 4; kc++) {
        uint32_t af0, af1, af2, af3;
        ldsm4(af0, af1, af2, af3, ab + kc * 32);
        uint32_t af[4] = {af0, af1, af2, af3};
        uint32_t b0, b1, b2, b3;
        ldsm4(b0, b1, b2, b3, bb2 + kc * 32);
        mma_f16(acc + 0, af, b0, b1);
        mma_f16(acc + 4, af, b2, b3);
        ldsm4(b0, b1, b2, b3, bb2 + 16 * KVS * 2 + kc * 32);
        mma_f16(acc + 8,  af, b0, b1);
        mma_f16(acc + 12, af, b2, b3);
    }
    __syncthreads();
    {
        float bv0 = bss[wm * 16 + g], bv1 = bss[wm * 16 + g + 8];
#pragma unroll
        for (int p = 0; p < 2; p++)
#pragma unroll
            for (int blk = 0; blk < 2; blk++) {
                int lb = wn * 32 + p * 16 + blk * 8 + 2 * r;
                int i = (p * 2 + blk) * 4;
                *(float2*)&T[(wm * 16 + g) * 68 + lb]     = make_float2(acc[i] + bv0, acc[i + 1] + bv0);
                *(float2*)&T[(wm * 16 + g + 8) * 68 + lb] = make_float2(acc[i + 2] + bv1, acc[i + 3] + bv1);
            }
    }
    __syncthreads();
    {
        int l = tid >> 2, cs = (tid & 3) * 16;
        __half* hp = H + ((size_t)b * Lseq + l0 + l) * 256 + mb * 64 + cs;
#pragma unroll
        for (int c = 0; c < 16; c += 2) {
            float v0 = fmaxf(T[(cs + c) * 68 + l], 0.f);
            float v1 = fmaxf(T[(cs + c + 1) * 68 + l], 0.f);
            *(uint32_t*)(hp + c) = hpack(v0, v1);
        }
    }
}

// ---------------- launch ----------------
extern "C" void kernel_launch(void* const* d_in, const int* in_sizes, int n_in,
                              void* d_out, int out_size)
{
    const float* q       = (const float*)d_in[0];
    const float* wq_pw   = (const float*)d_in[1];
    const float* wq_gate = (const float*)d_in[2];
    const float* wq_dw3  = (const float*)d_in[3];
    const float* wq_dw15 = (const float*)d_in[4];
    const float* wk_pw   = (const float*)d_in[5];
    const float* wk_gate = (const float*)d_in[6];
    const float* wk_dw3  = (const float*)d_in[7];
    const float* wk_dw15 = (const float*)d_in[8];
    const float* wv_pw   = (const float*)d_in[9];
    const float* wv_gate = (const float*)d_in[10];
    const float* wv_dw3  = (const float*)d_in[11];
    const float* wv_dw15 = (const float*)d_in[12];
    const float* w_unify = (const float*)d_in[13];
    const float* b_unify = (const float*)d_in[14];
    const float* ln1_g   = (const float*)d_in[15];
    const float* ln1_b   = (const float*)d_in[16];
    const float* ln2_g   = (const float*)d_in[17];
    const float* ln2_b   = (const float*)d_in[18];
    const float* ffn_w1  = (const float*)d_in[19];
    const float* ffn_b1  = (const float*)d_in[20];
    const float* ffn_w2  = (const float*)d_in[21];
    const float* ffn_b2  = (const float*)d_in[22];
    float* out = (float*)d_out;

    void *pPW, *pWF, *pqT, *pQ, *pK, *pV, *pATT, *pY, *pYh, *pH, *pWu, *pW1, *pW2;
    cudaGetSymbolAddress(&pPW, g_PW);
    cudaGetSymbolAddress(&pWF, g_WF);
    cudaGetSymbolAddress(&pqT, g_qT);
    cudaGetSymbolAddress(&pQ, g_Q);
    cudaGetSymbolAddress(&pK, g_K);
    cudaGetSymbolAddress(&pV, g_V);
    cudaGetSymbolAddress(&pATT, g_ATT);
    cudaGetSymbolAddress(&pY, g_Y);
    cudaGetSymbolAddress(&pYh, g_Yh);
    cudaGetSymbolAddress(&pH, g_H);
    cudaGetSymbolAddress(&pWu, g_Wu);
    cudaGetSymbolAddress(&pW1, g_W1);
    cudaGetSymbolAddress(&pW2, g_W2);

    cudaFuncSetAttribute(qkv_mma, cudaFuncAttributeMaxDynamicSharedMemorySize, 40960);

    combine_kernel<<<6, 256>>>(
        wq_pw, wq_gate, wq_dw3, wq_dw15,
        wk_pw, wk_gate, wk_dw3, wk_dw15,
        wv_pw, wv_gate, wv_dw3, wv_dw15,
        (float*)pPW, (float*)pWF);

    convw_kernel<<<256, 256>>>(w_unify, ffn_w1, ffn_w2);

    transpose_kernel<<<dim3(32, 16), 256>>>(q, (__half*)pqT);

    qkv_mma<<<dim3(8, 24, 16), 256, 40960>>>(
        (const __half*)pqT, (const float*)pPW, (const float*)pWF,
        (__half*)pQ, (__half*)pK, (__half*)pV);

    attn_f16<<<dim3(8, 128), 256>>>(
        (const __half*)pQ, (const __half*)pK, (const __half*)pV, (__half*)pATT);

    gemm_ln_kernel<<<dim3(16, 16), 256>>>(
        (const __half*)pATT, (const __half*)pWu,
        b_unify, q, ln1_g, ln1_b,
        (float*)pY, (__half*)pYh, 512);

    ffn1_mma<<<dim3(16, 4, 16), 256>>>(
        (const __half*)pYh, (const __half*)pW1,
        ffn_b1, (__half*)pH);

    gemm_ln_kernel<<<dim3(16, 16), 256>>>(
        (const __half*)pH, (const __half*)pW2,
        ffn_b2, (const float*)pY, ln2_g, ln2_b,
        out, (__half*)nullptr, 256);
}

// round 15
// speedup vs baseline: 1.4676x; 1.0001x over previous
#include <cuda_runtime.h>
#include <cuda_fp16.h>
#include <math.h>
#include <stdint.h>

#define Bsz  16
#define Cdim 64
#define Lseq 1024
#define Hn   8
#define HC   512
#define NH   128   // B*H batch-heads

// ---------------- scratch (static device memory; no allocations) ----------------
__device__ float g_PW[1536 * 64];
__device__ float g_WF[1536 * 15];
__device__ __half g_qT[Bsz * Lseq * Cdim];     // input transposed (b, l, c) fp16
__device__ __half g_Q[NH * Lseq * Cdim];       // (n, l, c) fp16, pre-scaled x0.125
__device__ __half g_K[NH * Lseq * Cdim];       // (n, l, c) fp16
__device__ __half g_V[NH * Cdim * Lseq];       // (n, c, l) fp16
__device__ __half g_ATT[Bsz * Lseq * HC];      // (b, l, hc) fp16
__device__ float g_Y[Bsz * Cdim * Lseq];       // LN1 out fp32 (b, c, l)
__device__ __half g_Yh[Bsz * Lseq * Cdim];     // LN1 out fp16 (b, l, c)
__device__ __half g_H[Bsz * Lseq * 256];       // FFN hidden fp16 (b, l, 256)
__device__ __half g_Wu[64 * 512];
__device__ __half g_W1[256 * 64];
__device__ __half g_W2[64 * 256];

__device__ __forceinline__ uint32_t hpack(float lo, float hi) {
    __half2 h = __floats2half2_rn(lo, hi);
    return *reinterpret_cast<uint32_t*>(&h);
}
__device__ __forceinline__ uint32_t smem_u32(const void* p) {
    uint32_t a;
    asm("{ .reg .u64 t; cvta.to.shared.u64 t, %1; cvt.u32.u64 %0, t; }" : "=r"(a) : "l"(p));
    return a;
}
__device__ __forceinline__ void mma_f16(float* c, const uint32_t* a, uint32_t b0, uint32_t b1) {
    asm volatile(
        "mma.sync.aligned.m16n8k16.row.col.f32.f16.f16.f32 "
        "{%0,%1,%2,%3}, {%4,%5,%6,%7}, {%8,%9}, {%0,%1,%2,%3};"
        : "+f"(c[0]), "+f"(c[1]), "+f"(c[2]), "+f"(c[3])
        : "r"(a[0]), "r"(a[1]), "r"(a[2]), "r"(a[3]), "r"(b0), "r"(b1));
}
__device__ __forceinline__ void ldsm4(uint32_t& r0, uint32_t& r1, uint32_t& r2, uint32_t& r3,
                                      uint32_t addr) {
    asm volatile("ldmatrix.sync.aligned.m8n8.x4.shared.b16 {%0,%1,%2,%3}, [%4];"
                 : "=r"(r0), "=r"(r1), "=r"(r2), "=r"(r3) : "r"(addr));
}
#define CP16(dst, src) \
    asm volatile("cp.async.cg.shared.global [%0], [%1], 16;" :: "r"(dst), "l"(src))
#define CP_COMMIT() asm volatile("cp.async.commit_group;" ::: "memory")
#define CP_WAIT1()  asm volatile("cp.async.wait_group 1;" ::: "memory")

// ---------------- K0: fold gate softmax into combined conv weights ----------------
__global__ void combine_kernel(
    const float* __restrict__ pw0, const float* __restrict__ gt0,
    const float* __restrict__ d3_0, const float* __restrict__ d15_0,
    const float* __restrict__ pw1, const float* __restrict__ gt1,
    const float* __restrict__ d3_1, const float* __restrict__ d15_1,
    const float* __restrict__ pw2, const float* __restrict__ gt2,
    const float* __restrict__ d3_2, const float* __restrict__ d15_2,
    float* __restrict__ PW, float* __restrict__ WF)
{
    int o = blockIdx.x * 256 + threadIdx.x;
    if (o >= 1536) return;
    int s = o >> 9, lc = o & 511;
    const float *pw, *gt, *d3, *d15;
    if (s == 0)      { pw = pw0; gt = gt0; d3 = d3_0; d15 = d15_0; }
    else if (s == 1) { pw = pw1; gt = gt1; d3 = d3_1; d15 = d15_1; }
    else             { pw = pw2; gt = gt2; d3 = d3_2; d15 = d15_2; }
    float a = gt[0], b = gt[1];
    float mx = fmaxf(a, b);
    float e0 = expf(a - mx), e1 = expf(b - mx);
    float inv = 1.0f / (e0 + e1);
    float ga = e0 * inv, gb = e1 * inv;
    for (int c = 0; c < 64; c++) PW[(size_t)o * 64 + c] = pw[(size_t)lc * 64 + c];
    for (int t = 0; t < 15; t++) {
        float w = gb * d15[lc * 15 + t];
        if (t >= 6 && t < 9) w += ga * d3[lc * 3 + (t - 6)];
        WF[o * 15 + t] = w;
    }
}

// ---------------- K0b: weights -> fp16 ----------------
__global__ void convw_kernel(const float* __restrict__ wu, const float* __restrict__ w1,
                             const float* __restrict__ w2)
{
    int i = blockIdx.x * 256 + threadIdx.x;
    if (i < 32768)       g_Wu[i] = __float2half_rn(wu[i]);
    else if (i < 49152)  g_W1[i - 32768] = __float2half_rn(w1[i - 32768]);
    else if (i < 65536)  g_W2[i - 49152] = __float2half_rn(w2[i - 49152]);
}

// ---------------- K0c: transpose q (b,c,l) f32 -> (b,l,c) fp16 ----------------
__global__ __launch_bounds__(256) void transpose_kernel(
    const float* __restrict__ q, __half* __restrict__ qT)
{
    __shared__ float tile[64][33];
    int b = blockIdx.y, l0 = blockIdx.x * 32;
    int t = threadIdx.x;
    int c = t >> 2, lo4 = (t & 3) * 8;
    float4 v0 = *(const float4*)&q[((size_t)b * 64 + c) * Lseq + l0 + lo4];
    float4 v1 = *(const float4*)&q[((size_t)b * 64 + c) * Lseq + l0 + lo4 + 4];
    // scalar stores: 33-stride rows are NOT 16B-aligned for odd c
    tile[c][lo4 + 0] = v0.x; tile[c][lo4 + 1] = v0.y;
    tile[c][lo4 + 2] = v0.z; tile[c][lo4 + 3] = v0.w;
    tile[c][lo4 + 4] = v1.x; tile[c][lo4 + 5] = v1.y;
    tile[c][lo4 + 6] = v1.z; tile[c][lo4 + 7] = v1.w;
    __syncthreads();
    int l = t >> 3, c0 = (t & 7) * 8;
    uint32_t hp[4];
#pragma unroll
    for (int j = 0; j < 4; j++)
        hp[j] = hpack(tile[c0 + 2 * j][l], tile[c0 + 2 * j + 1][l]);
    *(uint4*)&qT[((size_t)b * Lseq + l0 + l) * 64 + c0] = *(uint4*)hp;
}

// ---------------- K1: qkv via fp16 mma pointwise + fp32 depthwise conv ----------------
// grid (8 Ltiles of 128, 24 o-blocks of 64, 16 b); 256 threads. dyn smem 40960.
#define BST 72          // fp16 row stride in staging tiles
__global__ __launch_bounds__(256) void qkv_mma(
    const __half* __restrict__ qT,
    const float* __restrict__ PW, const float* __restrict__ WF,
    __half* __restrict__ Qp, __half* __restrict__ Kp, __half* __restrict__ Vp)
{
    extern __shared__ __align__(16) char SM[];
    __half* As = (__half*)SM;               // [64][72]
    __half* Bs = (__half*)(SM + 9216);      // [160][72]
    float*  mid = (float*)SM;               // [64][160] (reused after mma)
    __shared__ float swf[64 * 16];
    int tid = threadIdx.x, w = tid >> 5, lane = tid & 31;
    int wm = w >> 1, wn = w & 1;
    int g = lane >> 2, r = lane & 3;
    int l0 = blockIdx.x * 128;
    int o0 = blockIdx.y * 64;
    int b  = blockIdx.z;

    // stage A (weights fp32 -> fp16), conv weights
    for (int e = tid; e < 4096; e += 256) {
        int o = e >> 6, c = e & 63;
        As[o * BST + c] = __float2half_rn(PW[(size_t)(o0 + o) * 64 + c]);
    }
    for (int e = tid; e < 64 * 15; e += 256) {
        int o = e / 15, t = e - o * 15;
        swf[o * 16 + t] = WF[(size_t)(o0 + o) * 15 + t];
    }
    // stage B: rows j=0..159 <-> position l0-7+j (zero pad OOB / j>=144)
    const __half* qTb = qT + (size_t)b * Lseq * 64;
#pragma unroll
    for (int k = 0; k < 5; k++) {
        int gi = tid + k * 256;
        int row = gi >> 3, gr = gi & 7;
        int l = l0 - 7 + row;
        uint4 v = make_uint4(0, 0, 0, 0);
        if (row < 144 && l >= 0 && l < Lseq)
            v = *(const uint4*)&qTb[(size_t)l * 64 + gr * 8];
        *(uint4*)&Bs[row * BST + gr * 8] = v;
    }
    __syncthreads();

    uint32_t asb = smem_u32(As), bsb = smem_u32(Bs);
    uint32_t a_off = asb + (((wm * 16 + (lane & 15)) * BST + ((lane >> 4) << 3)) * 2);
    uint32_t b_off = bsb + (((wn * 80 + (((lane >> 4) & 1) << 3) + (lane & 7)) * BST +
                             (((lane >> 3) & 1) << 3)) * 2);
    float acc[40];
#pragma unroll
    for (int i = 0; i < 40; i++) acc[i] = 0.f;
#pragma unroll
    for (int kc = 0; kc < 4; kc++) {
        uint32_t af0, af1, af2, af3;
        ldsm4(af0, af1, af2, af3, a_off + kc * 32);
        uint32_t af[4] = {af0, af1, af2, af3};
#pragma unroll
        for (int nb2 = 0; nb2 < 5; nb2++) {
            uint32_t b0, b1, b2, b3;
            ldsm4(b0, b1, b2, b3, b_off + nb2 * (16 * BST * 2) + kc * 32);
            mma_f16(acc + (nb2 * 2 + 0) * 4, af, b0, b1);
            mma_f16(acc + (nb2 * 2 + 1) * 4, af, b2, b3);
        }
    }
    __syncthreads();   // staging dead; write mid

    {
        int ro0 = wm * 16 + g, ro1 = ro0 + 8;
#pragma unroll
        for (int nb2 = 0; nb2 < 5; nb2++)
#pragma unroll
            for (int blk = 0; blk < 2; blk++) {
                int col = wn * 80 + nb2 * 16 + blk * 8 + 2 * r;
                int i = (nb2 * 2 + blk) * 4;
                *(float2*)&mid[ro0 * 160 + col] = make_float2(acc[i], acc[i + 1]);
                *(float2*)&mid[ro1 * 160 + col] = make_float2(acc[i + 2], acc[i + 3]);
            }
    }
    __syncthreads();

    // depthwise conv15 + scatter (block covers exactly one head's 64 channels)
    int s = o0 >> 9;
    float scale = (s == 0) ? 0.125f : 1.0f;
    int ch = o0 & 511, head = ch >> 6;
    size_t n = (size_t)b * 8 + head;
    for (int e = tid; e < 64 * 128; e += 256) {
        int o = e >> 7, i = e & 127;
        const float* mrow = mid + o * 160;
        const float* wrow = swf + o * 16;
        float acc2 = 0.f;
#pragma unroll
        for (int t = 0; t < 15; t++) acc2 += wrow[t] * mrow[i + t];
        __half hv = __float2half_rn(acc2 * scale);
        if (s == 2) {
            Vp[(n * 64 + o) * Lseq + l0 + i] = hv;              // (n, c, l)
        } else {
            __half* base = (s == 0) ? Qp : Kp;
            base[(n * Lseq + l0 + i) * 64 + o] = hv;            // (n, l, c)
        }
    }
}

// ---------------- K2: flash attention fp16 ----------------
#define KVS 72
#define BUFE (64 * KVS)
__global__ __launch_bounds__(256, 2) void attn_f16(
    const __half* __restrict__ Qt, const __half* __restrict__ Kt,
    const __half* __restrict__ Vg, __half* __restrict__ att)
{
    __shared__ __half Ks[2][BUFE];
    __shared__ __half Vs[2][BUFE];
    int tid = threadIdx.x, w = tid >> 5, lane = tid & 31;
    int g = lane >> 2, r = lane & 3;
    int n = blockIdx.y, q0 = blockIdx.x * 128;

    const __half* Qb = Qt + (size_t)n * (Lseq * 64) + (size_t)(q0 + w * 16) * 64;
    const __half* Kb = Kt + (size_t)n * (Lseq * 64);
    const __half* Vb = Vg + (size_t)n * (64 * Lseq);

    int kr0 = tid >> 3, kg0 = tid & 7;
    int kr1 = (tid + 256) >> 3, kg1 = (tid + 256) & 7;
    uint32_t ks_base = smem_u32(&Ks[0][0]);
    uint32_t vs_base = smem_u32(&Vs[0][0]);
    uint32_t kd0 = ks_base + (kr0 * KVS + kg0 * 8) * 2;
    uint32_t kd1 = ks_base + (kr1 * KVS + kg1 * 8) * 2;
    uint32_t vd0 = vs_base + (kr0 * KVS + kg0 * 8) * 2;
    uint32_t vd1 = vs_base + (kr1 * KVS + kg1 * 8) * 2;

    int sel = lane >> 3, lrow = lane & 7;
    int mrow = ((sel >> 1) << 3) + lrow;
    int mcol = (sel & 1) << 3;
    uint32_t kls = ks_base + (mrow * KVS + mcol) * 2;
    uint32_t vls = vs_base + (mrow * KVS + mcol) * 2;

    uint32_t qf[16];
#pragma unroll
    for (int kc = 0; kc < 4; kc++) {
        qf[kc * 4 + 0] = *(const uint32_t*)(Qb + (size_t)g * 64 + kc * 16 + 2 * r);
        qf[kc * 4 + 1] = *(const uint32_t*)(Qb + (size_t)(g + 8) * 64 + kc * 16 + 2 * r);
        qf[kc * 4 + 2] = *(const uint32_t*)(Qb + (size_t)g * 64 + kc * 16 + 2 * r + 8);
        qf[kc * 4 + 3] = *(const uint32_t*)(Qb + (size_t)(g + 8) * 64 + kc * 16 + 2 * r + 8);
    }

#pragma unroll
    for (int t = 0; t < 2; t++) {
        int k0 = t * 64;
        uint32_t bo = t * BUFE * 2;
        CP16(kd0 + bo, Kb + (size_t)(k0 + kr0) * 64 + kg0 * 8);
        CP16(kd1 + bo, Kb + (size_t)(k0 + kr1) * 64 + kg1 * 8);
        CP16(vd0 + bo, Vb + (size_t)kr0 * Lseq + k0 + kg0 * 8);
        CP16(vd1 + bo, Vb + (size_t)kr1 * Lseq + k0 + kg1 * 8);
        CP_COMMIT();
    }

    float oacc[32];
#pragma unroll
    for (int i = 0; i < 32; i++) oacc[i] = 0.f;
    float m0 = -INFINITY, m1 = -INFINITY, l0 = 0.f, l1 = 0.f;

    for (int kt = 0; kt < 16; kt++) {
        CP_WAIT1();
        __syncthreads();
        uint32_t bo = (kt & 1) * BUFE * 2;

        float sacc[32];
#pragma unroll
        for (int i = 0; i < 32; i++) sacc[i] = 0.f;
#pragma unroll
        for (int kc = 0; kc < 4; kc++) {
#pragma unroll
            for (int nb2 = 0; nb2 < 4; nb2++) {
                uint32_t b0, b1, b2, b3;
                ldsm4(b0, b1, b2, b3, kls + bo + nb2 * (16 * KVS * 2) + kc * 32);
                mma_f16(sacc + (2 * nb2) * 4,     qf + kc * 4, b0, b1);
                mma_f16(sacc + (2 * nb2 + 1) * 4, qf + kc * 4, b2, b3);
            }
        }

        float tm0 = -INFINITY, tm1 = -INFINITY;
#pragma unroll
        for (int nb = 0; nb < 8; nb++) {
            tm0 = fmaxf(tm0, fmaxf(sacc[nb * 4 + 0], sacc[nb * 4 + 1]));
            tm1 = fmaxf(tm1, fmaxf(sacc[nb * 4 + 2], sacc[nb * 4 + 3]));
        }
        tm0 = fmaxf(tm0, __shfl_xor_sync(0xffffffffu, tm0, 1));
        tm0 = fmaxf(tm0, __shfl_xor_sync(0xffffffffu, tm0, 2));
        tm1 = fmaxf(tm1, __shfl_xor_sync(0xffffffffu, tm1, 1));
        tm1 = fmaxf(tm1, __shfl_xor_sync(0xffffffffu, tm1, 2));
        float mn0 = fmaxf(m0, tm0), mn1 = fmaxf(m1, tm1);
        float al0 = __expf(m0 - mn0), al1 = __expf(m1 - mn1);
        m0 = mn0; m1 = mn1;
        float s0 = 0.f, s1 = 0.f;
        uint32_t plo[8], phi[8];
#pragma unroll
        for (int nb = 0; nb < 8; nb++) {
            float p0 = __expf(sacc[nb * 4 + 0] - mn0);
            float p1 = __expf(sacc[nb * 4 + 1] - mn0);
            float p2 = __expf(sacc[nb * 4 + 2] - mn1);
            float p3 = __expf(sacc[nb * 4 + 3] - mn1);
            s0 += p0 + p1; s1 += p2 + p3;
            plo[nb] = hpack(p0, p1);
            phi[nb] = hpack(p2, p3);
        }
        s0 += __shfl_xor_sync(0xffffffffu, s0, 1);
        s0 += __shfl_xor_sync(0xffffffffu, s0, 2);
        s1 += __shfl_xor_sync(0xffffffffu, s1, 1);
        s1 += __shfl_xor_sync(0xffffffffu, s1, 2);
        l0 = l0 * al0 + s0;
        l1 = l1 * al1 + s1;
#pragma unroll
        for (int nb = 0; nb < 8; nb++) {
            oacc[nb * 4 + 0] *= al0; oacc[nb * 4 + 1] *= al0;
            oacc[nb * 4 + 2] *= al1; oacc[nb * 4 + 3] *= al1;
        }

#pragma unroll
        for (int kc = 0; kc < 4; kc++) {
            uint32_t pa[4] = {plo[2 * kc], phi[2 * kc], plo[2 * kc + 1], phi[2 * kc + 1]};
#pragma unroll
            for (int nb2 = 0; nb2 < 4; nb2++) {
                uint32_t b0, b1, b2, b3;
                ldsm4(b0, b1, b2, b3, vls + bo + nb2 * (16 * KVS * 2) + kc * 32);
                mma_f16(oacc + (2 * nb2) * 4,     pa, b0, b1);
                mma_f16(oacc + (2 * nb2 + 1) * 4, pa, b2, b3);
            }
        }

        __syncthreads();
        if (kt < 14) {
            int k0 = (kt + 2) * 64;
            uint32_t nb_ = (kt & 1) * BUFE * 2;
            CP16(kd0 + nb_, Kb + (size_t)(k0 + kr0) * 64 + kg0 * 8);
            CP16(kd1 + nb_, Kb + (size_t)(k0 + kr1) * 64 + kg1 * 8);
            CP16(vd0 + nb_, Vb + (size_t)kr0 * Lseq + k0 + kg0 * 8);
            CP16(vd1 + nb_, Vb + (size_t)kr1 * Lseq + k0 + kg1 * 8);
        }
        CP_COMMIT();
    }

    float inv0 = 1.0f / l0, inv1 = 1.0f / l1;
    int bb = n >> 3, head = n & 7;
    int qg0 = q0 + w * 16 + g, qg1 = qg0 + 8;
#pragma unroll
    for (int nb = 0; nb < 8; nb++) {
        int c = head * 64 + nb * 8 + 2 * r;
        *(uint32_t*)&att[((size_t)bb * Lseq + qg0) * 512 + c] =
            hpack(oacc[nb * 4 + 0] * inv0, oacc[nb * 4 + 1] * inv0);
        *(uint32_t*)&att[((size_t)bb * Lseq + qg1) * 512 + c] =
            hpack(oacc[nb * 4 + 2] * inv1, oacc[nb * 4 + 3] * inv1);
    }
}

// ---------------- K3/K5: fp16 mma GEMM (64 x Kdim) + bias + residual + channel LN ----------------
__global__ __launch_bounds__(256) void gemm_ln_kernel(
    const __half* __restrict__ X,    // (b, 1024, Kdim) fp16
    const __half* __restrict__ Wg,   // (64, Kdim) fp16
    const float* __restrict__ bias, const float* __restrict__ res,
    const float* __restrict__ gam, const float* __restrict__ bet,
    float* __restrict__ outF,
    __half* __restrict__ outH,
    int Kdim)
{
    __shared__ __align__(16) char SM[36864];
    __shared__ float ps1[4 * 64], ps2[4 * 64], mu_s[64], iv_s[64];
    __shared__ float gs[64], bts[64], bss[64];
    int tid = threadIdx.x, w = tid >> 5, lane = tid & 31;
    int wm = w >> 1, wn = w & 1;
    int g = lane >> 2, r = lane & 3;
    int l0 = blockIdx.x * 64;
    int b  = blockIdx.y;
    int nch = Kdim >> 6;

    if (tid < 64) { gs[tid] = gam[tid]; bts[tid] = bet[tid]; bss[tid] = bias[tid]; }

    uint32_t asb = smem_u32(SM);
    uint32_t bsb = asb + 18432;
    uint32_t a_off = (uint32_t)(((wm * 16 + (lane & 15)) * KVS + ((lane >> 4) << 3)) * 2);
    uint32_t b_off = (uint32_t)(((wn * 32 + (((lane >> 4) & 1) << 3) + (lane & 7)) * KVS +
                                 (((lane >> 3) & 1) << 3)) * 2);
    int sr0 = tid >> 3, sg0 = tid & 7;
    int sr1 = (tid + 256) >> 3, sg1 = (tid + 256) & 7;
    uint32_t ad0 = asb + (sr0 * KVS + sg0 * 8) * 2;
    uint32_t ad1 = asb + (sr1 * KVS + sg1 * 8) * 2;
    uint32_t bd0 = bsb + (sr0 * KVS + sg0 * 8) * 2;
    uint32_t bd1 = bsb + (sr1 * KVS + sg1 * 8) * 2;
    const __half* Xb = X + (size_t)b * Lseq * Kdim;

#pragma unroll
    for (int t = 0; t < 2; t++) {
        int cb = t * 64;
        uint32_t bo = t * 9216;
        CP16(ad0 + bo, Wg + (size_t)sr0 * Kdim + cb + sg0 * 8);
        CP16(ad1 + bo, Wg + (size_t)sr1 * Kdim + cb + sg1 * 8);
        CP16(bd0 + bo, Xb + (size_t)(l0 + sr0) * Kdim + cb + sg0 * 8);
        CP16(bd1 + bo, Xb + (size_t)(l0 + sr1) * Kdim + cb + sg1 * 8);
        CP_COMMIT();
    }

    float acc[16];
#pragma unroll
    for (int i = 0; i < 16; i++) acc[i] = 0.f;

    for (int c = 0; c < nch; c++) {
        CP_WAIT1();
        __syncthreads();
        uint32_t bo = (c & 1) * 9216;
        uint32_t ab = asb + bo + a_off;
        uint32_t bb2 = bsb + bo + b_off;
#pragma unroll
        for (int kc = 0; kc < 4; kc++) {
            uint32_t af0, af1, af2, af3;
            ldsm4(af0, af1, af2, af3, ab + kc * 32);
            uint32_t af[4] = {af0, af1, af2, af3};
            uint32_t b0, b1, b2, b3;
            ldsm4(b0, b1, b2, b3, bb2 + kc * 32);
            mma_f16(acc + 0, af, b0, b1);
            mma_f16(acc + 4, af, b2, b3);
            ldsm4(b0, b1, b2, b3, bb2 + 16 * KVS * 2 + kc * 32);
            mma_f16(acc + 8,  af, b0, b1);
            mma_f16(acc + 12, af, b2, b3);
        }
        __syncthreads();
        if (c + 2 < nch) {
            int cb = (c + 2) * 64;
            uint32_t nb_ = (c & 1) * 9216;
            CP16(ad0 + nb_, Wg + (size_t)sr0 * Kdim + cb + sg0 * 8);
            CP16(ad1 + nb_, Wg + (size_t)sr1 * Kdim + cb + sg1 * 8);
            CP16(bd0 + nb_, Xb + (size_t)(l0 + sr0) * Kdim + cb + sg0 * 8);
            CP16(bd1 + nb_, Xb + (size_t)(l0 + sr1) * Kdim + cb + sg1 * 8);
        }
        CP_COMMIT();
    }
    __syncthreads();

    float* T = (float*)SM;
    float* R = (float*)(SM + 18432);
    {
        float bv0 = bss[wm * 16 + g], bv1 = bss[wm * 16 + g + 8];
#pragma unroll
        for (int p = 0; p < 2; p++)
#pragma unroll
            for (int blk = 0; blk < 2; blk++) {
                int lb = wn * 32 + p * 16 + blk * 8 + 2 * r;
                int i = (p * 2 + blk) * 4;
                *(float2*)&T[(wm * 16 + g) * 68 + lb]     = make_float2(acc[i] + bv0, acc[i + 1] + bv0);
                *(float2*)&T[(wm * 16 + g + 8) * 68 + lb] = make_float2(acc[i + 2] + bv1, acc[i + 3] + bv1);
            }
    }
    for (int e = tid; e < 1024; e += 256) {
        int row = e >> 4, sg = e & 15;
        *(float4*)&R[row * 68 + sg * 4] =
            *(const float4*)&res[((size_t)b * 64 + row) * Lseq + l0 + sg * 4];
    }
    __syncthreads();

    {
        int l = tid & 63, p = tid >> 6;
        float s1 = 0.f, s2 = 0.f;
#pragma unroll
        for (int ch = p * 16; ch < p * 16 + 16; ch++) {
            float v = T[ch * 68 + l] + R[ch * 68 + l];
            s1 += v; s2 += v * v;
        }
        ps1[p * 64 + l] = s1; ps2[p * 64 + l] = s2;
    }
    __syncthreads();
    if (tid < 64) {
        float s1 = ps1[tid] + ps1[64 + tid] + ps1[128 + tid] + ps1[192 + tid];
        float s2 = ps2[tid] + ps2[64 + tid] + ps2[128 + tid] + ps2[192 + tid];
        float mu = s1 * (1.0f / 64.0f);
        float var = s2 * (1.0f / 64.0f) - mu * mu;
        mu_s[tid] = mu;
        iv_s[tid] = rsqrtf(var + 1e-5f);
    }
    __syncthreads();

    {
        int ch = tid >> 2, ls = (tid & 3) * 16;
        float gv = gs[ch], bv = bts[ch];
        float* op = outF + ((size_t)b * 64 + ch) * Lseq + l0 + ls;
#pragma unroll
        for (int j = 0; j < 16; j += 4) {
            float4 ov;
            float* tp = &T[ch * 68 + ls + j];
            float* rp = &R[ch * 68 + ls + j];
            ov.x = (tp[0] + rp[0] - mu_s[ls + j + 0]) * iv_s[ls + j + 0] * gv + bv;
            ov.y = (tp[1] + rp[1] - mu_s[ls + j + 1]) * iv_s[ls + j + 1] * gv + bv;
            ov.z = (tp[2] + rp[2] - mu_s[ls + j + 2]) * iv_s[ls + j + 2] * gv + bv;
            ov.w = (tp[3] + rp[3] - mu_s[ls + j + 3]) * iv_s[ls + j + 3] * gv + bv;
            *(float4*)(op + j) = ov;
        }
    }
    if (outH) {
        int l = tid >> 2, cs = (tid & 3) * 16;
        float mu = mu_s[l], iv = iv_s[l];
        __half* hp = outH + ((size_t)b * Lseq + l0 + l) * 64 + cs;
#pragma unroll
        for (int c = 0; c < 16; c += 2) {
            float v0 = (T[(cs + c) * 68 + l] + R[(cs + c) * 68 + l] - mu) * iv * gs[cs + c] + bts[cs + c];
            float v1 = (T[(cs + c + 1) * 68 + l] + R[(cs + c + 1) * 68 + l] - mu) * iv * gs[cs + c + 1] + bts[cs + c + 1];
            *(uint32_t*)(hp + c) = hpack(v0, v1);
        }
    }
}

// ---------------- K4: FFN up-projection fp16 mma + ReLU ----------------
__global__ __launch_bounds__(256) void ffn1_mma(
    const __half* __restrict__ X, const __half* __restrict__ Wg,
    const float* __restrict__ bias, __half* __restrict__ H)
{
    __shared__ __align__(16) __half As[64 * KVS];
    __shared__ __align__(16) __half Bs[64 * KVS];
    __shared__ float T[64 * 68];
    __shared__ float bss[64];
    int tid = threadIdx.x, w = tid >> 5, lane = tid & 31;
    int wm = w >> 1, wn = w & 1;
    int g = lane >> 2, r = lane & 3;
    int l0 = blockIdx.x * 64;
    int mb = blockIdx.y;
    int b  = blockIdx.z;

    if (tid < 64) bss[tid] = bias[mb * 64 + tid];
    for (int e = tid; e < 512; e += 256) {
        int row = e >> 3, kg = e & 7;
        *(uint4*)&As[row * KVS + kg * 8] =
            *(const uint4*)&Wg[(size_t)(mb * 64 + row) * 64 + kg * 8];
        *(uint4*)&Bs[row * KVS + kg * 8] =
            *(const uint4*)&X[((size_t)b * Lseq + l0 + row) * 64 + kg * 8];
    }
    __syncthreads();

    uint32_t ab = smem_u32(As) + (((wm * 16 + (lane & 15)) * KVS + ((lane >> 4) << 3)) * 2);
    uint32_t bb2 = smem_u32(Bs) + (((wn * 32 + (((lane >> 4) & 1) << 3) + (lane & 7)) * KVS +
                                    (((lane >> 3) & 1) << 3)) * 2);
    float acc[16];
#pragma unroll
    for (int i = 0; i < 16; i++) acc[i] = 0.f;
#pragma unroll
    for (int kc = 0; kc < 4; kc++) {
        uint32_t af0, af1, af2, af3;
        ldsm4(af0, af1, af2, af3, ab + kc * 32);
        uint32_t af[4] = {af0, af1, af2, af3};
        uint32_t b0, b1, b2, b3;
        ldsm4(b0, b1, b2, b3, bb2 + kc * 32);
        mma_f16(acc + 0, af, b0, b1);
        mma_f16(acc + 4, af, b2, b3);
        ldsm4(b0, b1, b2, b3, bb2 + 16 * KVS * 2 + kc * 32);
        mma_f16(acc + 8,  af, b0, b1);
        mma_f16(acc + 12, af, b2, b3);
    }
    __syncthreads();
    {
        float bv0 = bss[wm * 16 + g], bv1 = bss[wm * 16 + g + 8];
#pragma unroll
        for (int p = 0; p < 2; p++)
#pragma unroll
            for (int blk = 0; blk < 2; blk++) {
                int lb = wn * 32 + p * 16 + blk * 8 + 2 * r;
                int i = (p * 2 + blk) * 4;
                *(float2*)&T[(wm * 16 + g) * 68 + lb]     = make_float2(acc[i] + bv0, acc[i + 1] + bv0);
                *(float2*)&T[(wm * 16 + g + 8) * 68 + lb] = make_float2(acc[i + 2] + bv1, acc[i + 3] + bv1);
            }
    }
    __syncthreads();
    {
        int l = tid >> 2, cs = (tid & 3) * 16;
        __half* hp = H + ((size_t)b * Lseq + l0 + l) * 256 + mb * 64 + cs;
#pragma unroll
        for (int c = 0; c < 16; c += 2) {
            float v0 = fmaxf(T[(cs + c) * 68 + l], 0.f);
            float v1 = fmaxf(T[(cs + c + 1) * 68 + l], 0.f);
            *(uint32_t*)(hp + c) = hpack(v0, v1);
        }
    }
}

// ---------------- launch ----------------
extern "C" void kernel_launch(void* const* d_in, const int* in_sizes, int n_in,
                              void* d_out, int out_size)
{
    const float* q       = (const float*)d_in[0];
    const float* wq_pw   = (const float*)d_in[1];
    const float* wq_gate = (const float*)d_in[2];
    const float* wq_dw3  = (const float*)d_in[3];
    const float* wq_dw15 = (const float*)d_in[4];
    const float* wk_pw   = (const float*)d_in[5];
    const float* wk_gate = (const float*)d_in[6];
    const float* wk_dw3  = (const float*)d_in[7];
    const float* wk_dw15 = (const float*)d_in[8];
    const float* wv_pw   = (const float*)d_in[9];
    const float* wv_gate = (const float*)d_in[10];
    const float* wv_dw3  = (const float*)d_in[11];
    const float* wv_dw15 = (const float*)d_in[12];
    const float* w_unify = (const float*)d_in[13];
    const float* b_unify = (const float*)d_in[14];
    const float* ln1_g   = (const float*)d_in[15];
    const float* ln1_b   = (const float*)d_in[16];
    const float* ln2_g   = (const float*)d_in[17];
    const float* ln2_b   = (const float*)d_in[18];
    const float* ffn_w1  = (const float*)d_in[19];
    const float* ffn_b1  = (const float*)d_in[20];
    const float* ffn_w2  = (const float*)d_in[21];
    const float* ffn_b2  = (const float*)d_in[22];
    float* out = (float*)d_out;

    void *pPW, *pWF, *pqT, *pQ, *pK, *pV, *pATT, *pY, *pYh, *pH, *pWu, *pW1, *pW2;
    cudaGetSymbolAddress(&pPW, g_PW);
    cudaGetSymbolAddress(&pWF, g_WF);
    cudaGetSymbolAddress(&pqT, g_qT);
    cudaGetSymbolAddress(&pQ, g_Q);
    cudaGetSymbolAddress(&pK, g_K);
    cudaGetSymbolAddress(&pV, g_V);
    cudaGetSymbolAddress(&pATT, g_ATT);
    cudaGetSymbolAddress(&pY, g_Y);
    cudaGetSymbolAddress(&pYh, g_Yh);
    cudaGetSymbolAddress(&pH, g_H);
    cudaGetSymbolAddress(&pWu, g_Wu);
    cudaGetSymbolAddress(&pW1, g_W1);
    cudaGetSymbolAddress(&pW2, g_W2);

    cudaFuncSetAttribute(qkv_mma, cudaFuncAttributeMaxDynamicSharedMemorySize, 40960);

    combine_kernel<<<6, 256>>>(
        wq_pw, wq_gate, wq_dw3, wq_dw15,
        wk_pw, wk_gate, wk_dw3, wk_dw15,
        wv_pw, wv_gate, wv_dw3, wv_dw15,
        (float*)pPW, (float*)pWF);

    convw_kernel<<<256, 256>>>(w_unify, ffn_w1, ffn_w2);

    transpose_kernel<<<dim3(32, 16), 256>>>(q, (__half*)pqT);

    qkv_mma<<<dim3(8, 24, 16), 256, 40960>>>(
        (const __half*)pqT, (const float*)pPW, (const float*)pWF,
        (__half*)pQ, (__half*)pK, (__half*)pV);

    attn_f16<<<dim3(8, 128), 256>>>(
        (const __half*)pQ, (const __half*)pK, (const __half*)pV, (__half*)pATT);

    gemm_ln_kernel<<<dim3(16, 16), 256>>>(
        (const __half*)pATT, (const __half*)pWu,
        b_unify, q, ln1_g, ln1_b,
        (float*)pY, (__half*)pYh, 512);

    ffn1_mma<<<dim3(16, 4, 16), 256>>>(
        (const __half*)pYh, (const __half*)pW1,
        ffn_b1, (__half*)pH);

    gemm_ln_kernel<<<dim3(16, 16), 256>>>(
        (const __half*)pH, (const __half*)pW2,
        ffn_b2, (const float*)pY, ln2_g, ln2_b,
        out, (__half*)nullptr, 256);
}

// round 16
// speedup vs baseline: 1.4681x; 1.0003x over previous
#include <cuda_runtime.h>
#include <cuda_fp16.h>
#include <math.h>
#include <stdint.h>

#define Bsz  16
#define Cdim 64
#define Lseq 1024
#define Hn   8
#define HC   512
#define NH   128   // B*H batch-heads

// ---------------- scratch (static device memory; no allocations) ----------------
__device__ float g_PW[1536 * 64];
__device__ float g_WF[1536 * 15];
__device__ __half g_qT[Bsz * Lseq * Cdim];     // input transposed (b, l, c) fp16
__device__ __half g_Q[NH * Lseq * Cdim];       // (n, l, c) fp16, pre-scaled x0.125
__device__ __half g_K[NH * Lseq * Cdim];       // (n, l, c) fp16
__device__ __half g_V[NH * Cdim * Lseq];       // (n, c, l) fp16
__device__ __half g_ATT[Bsz * Lseq * HC];      // (b, l, hc) fp16
__device__ float g_Y[Bsz * Cdim * Lseq];       // LN1 out fp32 (b, c, l)
__device__ __half g_Yh[Bsz * Lseq * Cdim];     // LN1 out fp16 (b, l, c)
__device__ __half g_H[Bsz * Lseq * 256];       // FFN hidden fp16 (b, l, 256)
__device__ __half g_Wu[64 * 512];
__device__ __half g_W1[256 * 64];
__device__ __half g_W2[64 * 256];

__device__ __forceinline__ uint32_t hpack(float lo, float hi) {
    __half2 h = __floats2half2_rn(lo, hi);
    return *reinterpret_cast<uint32_t*>(&h);
}
__device__ __forceinline__ uint32_t smem_u32(const void* p) {
    uint32_t a;
    asm("{ .reg .u64 t; cvta.to.shared.u64 t, %1; cvt.u32.u64 %0, t; }" : "=r"(a) : "l"(p));
    return a;
}
__device__ __forceinline__ void mma_f16(float* c, const uint32_t* a, uint32_t b0, uint32_t b1) {
    asm volatile(
        "mma.sync.aligned.m16n8k16.row.col.f32.f16.f16.f32 "
        "{%0,%1,%2,%3}, {%4,%5,%6,%7}, {%8,%9}, {%0,%1,%2,%3};"
        : "+f"(c[0]), "+f"(c[1]), "+f"(c[2]), "+f"(c[3])
        : "r"(a[0]), "r"(a[1]), "r"(a[2]), "r"(a[3]), "r"(b0), "r"(b1));
}
__device__ __forceinline__ void ldsm4(uint32_t& r0, uint32_t& r1, uint32_t& r2, uint32_t& r3,
                                      uint32_t addr) {
    asm volatile("ldmatrix.sync.aligned.m8n8.x4.shared.b16 {%0,%1,%2,%3}, [%4];"
                 : "=r"(r0), "=r"(r1), "=r"(r2), "=r"(r3) : "r"(addr));
}
#define CP16(dst, src) \
    asm volatile("cp.async.cg.shared.global [%0], [%1], 16;" :: "r"(dst), "l"(src))
#define CP_COMMIT() asm volatile("cp.async.commit_group;" ::: "memory")
#define CP_WAIT1()  asm volatile("cp.async.wait_group 1;" ::: "memory")

// ---------------- K0: fold gate softmax into combined conv weights ----------------
__global__ void combine_kernel(
    const float* __restrict__ pw0, const float* __restrict__ gt0,
    const float* __restrict__ d3_0, const float* __restrict__ d15_0,
    const float* __restrict__ pw1, const float* __restrict__ gt1,
    const float* __restrict__ d3_1, const float* __restrict__ d15_1,
    const float* __restrict__ pw2, const float* __restrict__ gt2,
    const float* __restrict__ d3_2, const float* __restrict__ d15_2,
    float* __restrict__ PW, float* __restrict__ WF)
{
    int o = blockIdx.x * 256 + threadIdx.x;
    if (o >= 1536) return;
    int s = o >> 9, lc = o & 511;
    const float *pw, *gt, *d3, *d15;
    if (s == 0)      { pw = pw0; gt = gt0; d3 = d3_0; d15 = d15_0; }
    else if (s == 1) { pw = pw1; gt = gt1; d3 = d3_1; d15 = d15_1; }
    else             { pw = pw2; gt = gt2; d3 = d3_2; d15 = d15_2; }
    float a = gt[0], b = gt[1];
    float mx = fmaxf(a, b);
    float e0 = expf(a - mx), e1 = expf(b - mx);
    float inv = 1.0f / (e0 + e1);
    float ga = e0 * inv, gb = e1 * inv;
    for (int c = 0; c < 64; c++) PW[(size_t)o * 64 + c] = pw[(size_t)lc * 64 + c];
    for (int t = 0; t < 15; t++) {
        float w = gb * d15[lc * 15 + t];
        if (t >= 6 && t < 9) w += ga * d3[lc * 3 + (t - 6)];
        WF[o * 15 + t] = w;
    }
}

// ---------------- K0b: weights -> fp16 ----------------
__global__ void convw_kernel(const float* __restrict__ wu, const float* __restrict__ w1,
                             const float* __restrict__ w2)
{
    int i = blockIdx.x * 256 + threadIdx.x;
    if (i < 32768)       g_Wu[i] = __float2half_rn(wu[i]);
    else if (i < 49152)  g_W1[i - 32768] = __float2half_rn(w1[i - 32768]);
    else if (i < 65536)  g_W2[i - 49152] = __float2half_rn(w2[i - 49152]);
}

// ---------------- K0c: transpose q (b,c,l) f32 -> (b,l,c) fp16 ----------------
__global__ __launch_bounds__(256) void transpose_kernel(
    const float* __restrict__ q, __half* __restrict__ qT)
{
    __shared__ float tile[64][33];
    int b = blockIdx.y, l0 = blockIdx.x * 32;
    int t = threadIdx.x;
    int c = t >> 2, lo4 = (t & 3) * 8;
    float4 v0 = *(const float4*)&q[((size_t)b * 64 + c) * Lseq + l0 + lo4];
    float4 v1 = *(const float4*)&q[((size_t)b * 64 + c) * Lseq + l0 + lo4 + 4];
    // scalar stores: 33-stride rows are NOT 16B-aligned for odd c
    tile[c][lo4 + 0] = v0.x; tile[c][lo4 + 1] = v0.y;
    tile[c][lo4 + 2] = v0.z; tile[c][lo4 + 3] = v0.w;
    tile[c][lo4 + 4] = v1.x; tile[c][lo4 + 5] = v1.y;
    tile[c][lo4 + 6] = v1.z; tile[c][lo4 + 7] = v1.w;
    __syncthreads();
    int l = t >> 3, c0 = (t & 7) * 8;
    uint32_t hp[4];
#pragma unroll
    for (int j = 0; j < 4; j++)
        hp[j] = hpack(tile[c0 + 2 * j][l], tile[c0 + 2 * j + 1][l]);
    *(uint4*)&qT[((size_t)b * Lseq + l0 + l) * 64 + c0] = *(uint4*)hp;
}

// ---------------- K1: qkv via fp16 mma pointwise + fp32 depthwise conv ----------------
// grid (8 Ltiles of 128, 24 o-blocks of 64, 16 b); 256 threads. dyn smem 40960.
#define BST 72          // fp16 row stride in staging tiles
__global__ __launch_bounds__(256) void qkv_mma(
    const __half* __restrict__ qT,
    const float* __restrict__ PW, const float* __restrict__ WF,
    __half* __restrict__ Qp, __half* __restrict__ Kp, __half* __restrict__ Vp)
{
    extern __shared__ __align__(16) char SM[];
    __half* As = (__half*)SM;               // [64][72]
    __half* Bs = (__half*)(SM + 9216);      // [160][72]
    float*  mid = (float*)SM;               // [64][160] (reused after mma)
    __shared__ float swf[64 * 16];
    int tid = threadIdx.x, w = tid >> 5, lane = tid & 31;
    int wm = w >> 1, wn = w & 1;
    int g = lane >> 2, r = lane & 3;
    int l0 = blockIdx.x * 128;
    int o0 = blockIdx.y * 64;
    int b  = blockIdx.z;

    // stage A (weights fp32 -> fp16), conv weights
    for (int e = tid; e < 4096; e += 256) {
        int o = e >> 6, c = e & 63;
        As[o * BST + c] = __float2half_rn(PW[(size_t)(o0 + o) * 64 + c]);
    }
    for (int e = tid; e < 64 * 15; e += 256) {
        int o = e / 15, t = e - o * 15;
        swf[o * 16 + t] = WF[(size_t)(o0 + o) * 15 + t];
    }
    // stage B: rows j=0..159 <-> position l0-7+j (zero pad OOB / j>=144)
    const __half* qTb = qT + (size_t)b * Lseq * 64;
#pragma unroll
    for (int k = 0; k < 5; k++) {
        int gi = tid + k * 256;
        int row = gi >> 3, gr = gi & 7;
        int l = l0 - 7 + row;
        uint4 v = make_uint4(0, 0, 0, 0);
        if (row < 144 && l >= 0 && l < Lseq)
            v = *(const uint4*)&qTb[(size_t)l * 64 + gr * 8];
        *(uint4*)&Bs[row * BST + gr * 8] = v;
    }
    __syncthreads();

    uint32_t asb = smem_u32(As), bsb = smem_u32(Bs);
    uint32_t a_off = asb + (((wm * 16 + (lane & 15)) * BST + ((lane >> 4) << 3)) * 2);
    uint32_t b_off = bsb + (((wn * 80 + (((lane >> 4) & 1) << 3) + (lane & 7)) * BST +
                             (((lane >> 3) & 1) << 3)) * 2);
    float acc[40];
#pragma unroll
    for (int i = 0; i < 40; i++) acc[i] = 0.f;
#pragma unroll
    for (int kc = 0; kc < 4; kc++) {
        uint32_t af0, af1, af2, af3;
        ldsm4(af0, af1, af2, af3, a_off + kc * 32);
        uint32_t af[4] = {af0, af1, af2, af3};
#pragma unroll
        for (int nb2 = 0; nb2 < 5; nb2++) {
            uint32_t b0, b1, b2, b3;
            ldsm4(b0, b1, b2, b3, b_off + nb2 * (16 * BST * 2) + kc * 32);
            mma_f16(acc + (nb2 * 2 + 0) * 4, af, b0, b1);
            mma_f16(acc + (nb2 * 2 + 1) * 4, af, b2, b3);
        }
    }
    __syncthreads();   // staging dead; write mid

    {
        int ro0 = wm * 16 + g, ro1 = ro0 + 8;
#pragma unroll
        for (int nb2 = 0; nb2 < 5; nb2++)
#pragma unroll
            for (int blk = 0; blk < 2; blk++) {
                int col = wn * 80 + nb2 * 16 + blk * 8 + 2 * r;
                int i = (nb2 * 2 + blk) * 4;
                *(float2*)&mid[ro0 * 160 + col] = make_float2(acc[i], acc[i + 1]);
                *(float2*)&mid[ro1 * 160 + col] = make_float2(acc[i + 2], acc[i + 3]);
            }
    }
    __syncthreads();

    // depthwise conv15 + scatter (block covers exactly one head's 64 channels)
    int s = o0 >> 9;
    float scale = (s == 0) ? 0.125f : 1.0f;
    int ch = o0 & 511, head = ch >> 6;
    size_t n = (size_t)b * 8 + head;
    for (int e = tid; e < 64 * 128; e += 256) {
        int o = e >> 7, i = e & 127;
        const float* mrow = mid + o * 160;
        const float* wrow = swf + o * 16;
        float acc2 = 0.f;
#pragma unroll
        for (int t = 0; t < 15; t++) acc2 += wrow[t] * mrow[i + t];
        __half hv = __float2half_rn(acc2 * scale);
        if (s == 2) {
            Vp[(n * 64 + o) * Lseq + l0 + i] = hv;              // (n, c, l)
        } else {
            __half* base = (s == 0) ? Qp : Kp;
            base[(n * Lseq + l0 + i) * 64 + o] = hv;            // (n, l, c)
        }
    }
}

// ---------------- K2: flash attention fp16 ----------------
#define KVS 72
#define BUFE (64 * KVS)
__global__ __launch_bounds__(256, 2) void attn_f16(
    const __half* __restrict__ Qt, const __half* __restrict__ Kt,
    const __half* __restrict__ Vg, __half* __restrict__ att)
{
    __shared__ __half Ks[2][BUFE];
    __shared__ __half Vs[2][BUFE];
    int tid = threadIdx.x, w = tid >> 5, lane = tid & 31;
    int g = lane >> 2, r = lane & 3;
    int n = blockIdx.y, q0 = blockIdx.x * 128;

    const __half* Qb = Qt + (size_t)n * (Lseq * 64) + (size_t)(q0 + w * 16) * 64;
    const __half* Kb = Kt + (size_t)n * (Lseq * 64);
    const __half* Vb = Vg + (size_t)n * (64 * Lseq);

    int kr0 = tid >> 3, kg0 = tid & 7;
    int kr1 = (tid + 256) >> 3, kg1 = (tid + 256) & 7;
    uint32_t ks_base = smem_u32(&Ks[0][0]);
    uint32_t vs_base = smem_u32(&Vs[0][0]);
    uint32_t kd0 = ks_base + (kr0 * KVS + kg0 * 8) * 2;
    uint32_t kd1 = ks_base + (kr1 * KVS + kg1 * 8) * 2;
    uint32_t vd0 = vs_base + (kr0 * KVS + kg0 * 8) * 2;
    uint32_t vd1 = vs_base + (kr1 * KVS + kg1 * 8) * 2;

    int sel = lane >> 3, lrow = lane & 7;
    int mrow = ((sel >> 1) << 3) + lrow;
    int mcol = (sel & 1) << 3;
    uint32_t kls = ks_base + (mrow * KVS + mcol) * 2;
    uint32_t vls = vs_base + (mrow * KVS + mcol) * 2;

    uint32_t qf[16];
#pragma unroll
    for (int kc = 0; kc < 4; kc++) {
        qf[kc * 4 + 0] = *(const uint32_t*)(Qb + (size_t)g * 64 + kc * 16 + 2 * r);
        qf[kc * 4 + 1] = *(const uint32_t*)(Qb + (size_t)(g + 8) * 64 + kc * 16 + 2 * r);
        qf[kc * 4 + 2] = *(const uint32_t*)(Qb + (size_t)g * 64 + kc * 16 + 2 * r + 8);
        qf[kc * 4 + 3] = *(const uint32_t*)(Qb + (size_t)(g + 8) * 64 + kc * 16 + 2 * r + 8);
    }

#pragma unroll
    for (int t = 0; t < 2; t++) {
        int k0 = t * 64;
        uint32_t bo = t * BUFE * 2;
        CP16(kd0 + bo, Kb + (size_t)(k0 + kr0) * 64 + kg0 * 8);
        CP16(kd1 + bo, Kb + (size_t)(k0 + kr1) * 64 + kg1 * 8);
        CP16(vd0 + bo, Vb + (size_t)kr0 * Lseq + k0 + kg0 * 8);
        CP16(vd1 + bo, Vb + (size_t)kr1 * Lseq + k0 + kg1 * 8);
        CP_COMMIT();
    }

    float oacc[32];
#pragma unroll
    for (int i = 0; i < 32; i++) oacc[i] = 0.f;
    float m0 = -INFINITY, m1 = -INFINITY, l0 = 0.f, l1 = 0.f;

    for (int kt = 0; kt < 16; kt++) {
        CP_WAIT1();
        __syncthreads();
        uint32_t bo = (kt & 1) * BUFE * 2;

        float sacc[32];
#pragma unroll
        for (int i = 0; i < 32; i++) sacc[i] = 0.f;
#pragma unroll
        for (int kc = 0; kc < 4; kc++) {
#pragma unroll
            for (int nb2 = 0; nb2 < 4; nb2++) {
                uint32_t b0, b1, b2, b3;
                ldsm4(b0, b1, b2, b3, kls + bo + nb2 * (16 * KVS * 2) + kc * 32);
                mma_f16(sacc + (2 * nb2) * 4,     qf + kc * 4, b0, b1);
                mma_f16(sacc + (2 * nb2 + 1) * 4, qf + kc * 4, b2, b3);
            }
        }

        float tm0 = -INFINITY, tm1 = -INFINITY;
#pragma unroll
        for (int nb = 0; nb < 8; nb++) {
            tm0 = fmaxf(tm0, fmaxf(sacc[nb * 4 + 0], sacc[nb * 4 + 1]));
            tm1 = fmaxf(tm1, fmaxf(sacc[nb * 4 + 2], sacc[nb * 4 + 3]));
        }
        tm0 = fmaxf(tm0, __shfl_xor_sync(0xffffffffu, tm0, 1));
        tm0 = fmaxf(tm0, __shfl_xor_sync(0xffffffffu, tm0, 2));
        tm1 = fmaxf(tm1, __shfl_xor_sync(0xffffffffu, tm1, 1));
        tm1 = fmaxf(tm1, __shfl_xor_sync(0xffffffffu, tm1, 2));
        float mn0 = fmaxf(m0, tm0), mn1 = fmaxf(m1, tm1);
        float al0 = __expf(m0 - mn0), al1 = __expf(m1 - mn1);
        m0 = mn0; m1 = mn1;
        float s0 = 0.f, s1 = 0.f;
        uint32_t plo[8], phi[8];
#pragma unroll
        for (int nb = 0; nb < 8; nb++) {
            float p0 = __expf(sacc[nb * 4 + 0] - mn0);
            float p1 = __expf(sacc[nb * 4 + 1] - mn0);
            float p2 = __expf(sacc[nb * 4 + 2] - mn1);
            float p3 = __expf(sacc[nb * 4 + 3] - mn1);
            s0 += p0 + p1; s1 += p2 + p3;
            plo[nb] = hpack(p0, p1);
            phi[nb] = hpack(p2, p3);
        }
        s0 += __shfl_xor_sync(0xffffffffu, s0, 1);
        s0 += __shfl_xor_sync(0xffffffffu, s0, 2);
        s1 += __shfl_xor_sync(0xffffffffu, s1, 1);
        s1 += __shfl_xor_sync(0xffffffffu, s1, 2);
        l0 = l0 * al0 + s0;
        l1 = l1 * al1 + s1;
#pragma unroll
        for (int nb = 0; nb < 8; nb++) {
            oacc[nb * 4 + 0] *= al0; oacc[nb * 4 + 1] *= al0;
            oacc[nb * 4 + 2] *= al1; oacc[nb * 4 + 3] *= al1;
        }

#pragma unroll
        for (int kc = 0; kc < 4; kc++) {
            uint32_t pa[4] = {plo[2 * kc], phi[2 * kc], plo[2 * kc + 1], phi[2 * kc + 1]};
#pragma unroll
            for (int nb2 = 0; nb2 < 4; nb2++) {
                uint32_t b0, b1, b2, b3;
                ldsm4(b0, b1, b2, b3, vls + bo + nb2 * (16 * KVS * 2) + kc * 32);
                mma_f16(oacc + (2 * nb2) * 4,     pa, b0, b1);
                mma_f16(oacc + (2 * nb2 + 1) * 4, pa, b2, b3);
            }
        }

        __syncthreads();
        if (kt < 14) {
            int k0 = (kt + 2) * 64;
            uint32_t nb_ = (kt & 1) * BUFE * 2;
            CP16(kd0 + nb_, Kb + (size_t)(k0 + kr0) * 64 + kg0 * 8);
            CP16(kd1 + nb_, Kb + (size_t)(k0 + kr1) * 64 + kg1 * 8);
            CP16(vd0 + nb_, Vb + (size_t)kr0 * Lseq + k0 + kg0 * 8);
            CP16(vd1 + nb_, Vb + (size_t)kr1 * Lseq + k0 + kg1 * 8);
        }
        CP_COMMIT();
    }

    float inv0 = 1.0f / l0, inv1 = 1.0f / l1;
    int bb = n >> 3, head = n & 7;
    int qg0 = q0 + w * 16 + g, qg1 = qg0 + 8;
#pragma unroll
    for (int nb = 0; nb < 8; nb++) {
        int c = head * 64 + nb * 8 + 2 * r;
        *(uint32_t*)&att[((size_t)bb * Lseq + qg0) * 512 + c] =
            hpack(oacc[nb * 4 + 0] * inv0, oacc[nb * 4 + 1] * inv0);
        *(uint32_t*)&att[((size_t)bb * Lseq + qg1) * 512 + c] =
            hpack(oacc[nb * 4 + 2] * inv1, oacc[nb * 4 + 3] * inv1);
    }
}

// ---------------- K3/K5: fp16 mma GEMM (64 x Kdim) + bias + residual + channel LN ----------------
__global__ __launch_bounds__(256) void gemm_ln_kernel(
    const __half* __restrict__ X,    // (b, 1024, Kdim) fp16
    const __half* __restrict__ Wg,   // (64, Kdim) fp16
    const float* __restrict__ bias, const float* __restrict__ res,
    const float* __restrict__ gam, const float* __restrict__ bet,
    float* __restrict__ outF,
    __half* __restrict__ outH,
    int Kdim)
{
    __shared__ __align__(16) char SM[36864];
    __shared__ float ps1[4 * 64], ps2[4 * 64], mu_s[64], iv_s[64];
    __shared__ float gs[64], bts[64], bss[64];
    int tid = threadIdx.x, w = tid >> 5, lane = tid & 31;
    int wm = w >> 1, wn = w & 1;
    int g = lane >> 2, r = lane & 3;
    int l0 = blockIdx.x * 64;
    int b  = blockIdx.y;
    int nch = Kdim >> 6;

    if (tid < 64) { gs[tid] = gam[tid]; bts[tid] = bet[tid]; bss[tid] = bias[tid]; }

    uint32_t asb = smem_u32(SM);
    uint32_t bsb = asb + 18432;
    uint32_t a_off = (uint32_t)(((wm * 16 + (lane & 15)) * KVS + ((lane >> 4) << 3)) * 2);
    uint32_t b_off = (uint32_t)(((wn * 32 + (((lane >> 4) & 1) << 3) + (lane & 7)) * KVS +
                                 (((lane >> 3) & 1) << 3)) * 2);
    int sr0 = tid >> 3, sg0 = tid & 7;
    int sr1 = (tid + 256) >> 3, sg1 = (tid + 256) & 7;
    uint32_t ad0 = asb + (sr0 * KVS + sg0 * 8) * 2;
    uint32_t ad1 = asb + (sr1 * KVS + sg1 * 8) * 2;
    uint32_t bd0 = bsb + (sr0 * KVS + sg0 * 8) * 2;
    uint32_t bd1 = bsb + (sr1 * KVS + sg1 * 8) * 2;
    const __half* Xb = X + (size_t)b * Lseq * Kdim;

#pragma unroll
    for (int t = 0; t < 2; t++) {
        int cb = t * 64;
        uint32_t bo = t * 9216;
        CP16(ad0 + bo, Wg + (size_t)sr0 * Kdim + cb + sg0 * 8);
        CP16(ad1 + bo, Wg + (size_t)sr1 * Kdim + cb + sg1 * 8);
        CP16(bd0 + bo, Xb + (size_t)(l0 + sr0) * Kdim + cb + sg0 * 8);
        CP16(bd1 + bo, Xb + (size_t)(l0 + sr1) * Kdim + cb + sg1 * 8);
        CP_COMMIT();
    }

    float acc[16];
#pragma unroll
    for (int i = 0; i < 16; i++) acc[i] = 0.f;

    for (int c = 0; c < nch; c++) {
        CP_WAIT1();
        __syncthreads();
        uint32_t bo = (c & 1) * 9216;
        uint32_t ab = asb + bo + a_off;
        uint32_t bb2 = bsb + bo + b_off;
#pragma unroll
        for (int kc = 0; kc < 4; kc++) {
            uint32_t af0, af1, af2, af3;
            ldsm4(af0, af1, af2, af3, ab + kc * 32);
            uint32_t af[4] = {af0, af1, af2, af3};
            uint32_t b0, b1, b2, b3;
            ldsm4(b0, b1, b2, b3, bb2 + kc * 32);
            mma_f16(acc + 0, af, b0, b1);
            mma_f16(acc + 4, af, b2, b3);
            ldsm4(b0, b1, b2, b3, bb2 + 16 * KVS * 2 + kc * 32);
            mma_f16(acc + 8,  af, b0, b1);
            mma_f16(acc + 12, af, b2, b3);
        }
        __syncthreads();
        if (c + 2 < nch) {
            int cb = (c + 2) * 64;
            uint32_t nb_ = (c & 1) * 9216;
            CP16(ad0 + nb_, Wg + (size_t)sr0 * Kdim + cb + sg0 * 8);
            CP16(ad1 + nb_, Wg + (size_t)sr1 * Kdim + cb + sg1 * 8);
            CP16(bd0 + nb_, Xb + (size_t)(l0 + sr0) * Kdim + cb + sg0 * 8);
            CP16(bd1 + nb_, Xb + (size_t)(l0 + sr1) * Kdim + cb + sg1 * 8);
        }
        CP_COMMIT();
    }
    __syncthreads();

    float* T = (float*)SM;
    float* R = (float*)(SM + 18432);
    {
        float bv0 = bss[wm * 16 + g], bv1 = bss[wm * 16 + g + 8];
#pragma unroll
        for (int p = 0; p < 2; p++)
#pragma unroll
            for (int blk = 0; blk < 2; blk++) {
                int lb = wn * 32 + p * 16 + blk * 8 + 2 * r;
                int i = (p * 2 + blk) * 4;
                *(float2*)&T[(wm * 16 + g) * 68 + lb]     = make_float2(acc[i] + bv0, acc[i + 1] + bv0);
                *(float2*)&T[(wm * 16 + g + 8) * 68 + lb] = make_float2(acc[i + 2] + bv1, acc[i + 3] + bv1);
            }
    }
    for (int e = tid; e < 1024; e += 256) {
        int row = e >> 4, sg = e & 15;
        *(float4*)&R[row * 68 + sg * 4] =
            *(const float4*)&res[((size_t)b * 64 + row) * Lseq + l0 + sg * 4];
    }
    __syncthreads();

    {
        int l = tid & 63, p = tid >> 6;
        float s1 = 0.f, s2 = 0.f;
#pragma unroll
        for (int ch = p * 16; ch < p * 16 + 16; ch++) {
            float v = T[ch * 68 + l] + R[ch * 68 + l];
            s1 += v; s2 += v * v;
        }
        ps1[p * 64 + l] = s1; ps2[p * 64 + l] = s2;
    }
    __syncthreads();
    if (tid < 64) {
        float s1 = ps1[tid] + ps1[64 + tid] + ps1[128 + tid] + ps1[192 + tid];
        float s2 = ps2[tid] + ps2[64 + tid] + ps2[128 + tid] + ps2[192 + tid];
        float mu = s1 * (1.0f / 64.0f);
        float var = s2 * (1.0f / 64.0f) - mu * mu;
        mu_s[tid] = mu;
        iv_s[tid] = rsqrtf(var + 1e-5f);
    }
    __syncthreads();

    {
        int ch = tid >> 2, ls = (tid & 3) * 16;
        float gv = gs[ch], bv = bts[ch];
        float* op = outF + ((size_t)b * 64 + ch) * Lseq + l0 + ls;
#pragma unroll
        for (int j = 0; j < 16; j += 4) {
            float4 ov;
            float* tp = &T[ch * 68 + ls + j];
            float* rp = &R[ch * 68 + ls + j];
            ov.x = (tp[0] + rp[0] - mu_s[ls + j + 0]) * iv_s[ls + j + 0] * gv + bv;
            ov.y = (tp[1] + rp[1] - mu_s[ls + j + 1]) * iv_s[ls + j + 1] * gv + bv;
            ov.z = (tp[2] + rp[2] - mu_s[ls + j + 2]) * iv_s[ls + j + 2] * gv + bv;
            ov.w = (tp[3] + rp[3] - mu_s[ls + j + 3]) * iv_s[ls + j + 3] * gv + bv;
            *(float4*)(op + j) = ov;
        }
    }
    if (outH) {
        int l = tid >> 2, cs = (tid & 3) * 16;
        float mu = mu_s[l], iv = iv_s[l];
        __half* hp = outH + ((size_t)b * Lseq + l0 + l) * 64 + cs;
#pragma unroll
        for (int c = 0; c < 16; c += 2) {
            float v0 = (T[(cs + c) * 68 + l] + R[(cs + c) * 68 + l] - mu) * iv * gs[cs + c] + bts[cs + c];
            float v1 = (T[(cs + c + 1) * 68 + l] + R[(cs + c + 1) * 68 + l] - mu) * iv * gs[cs + c + 1] + bts[cs + c + 1];
            *(uint32_t*)(hp + c) = hpack(v0, v1);
        }
    }
}

// ---------------- K4: FFN up-projection fp16 mma + ReLU ----------------
__global__ __launch_bounds__(256) void ffn1_mma(
    const __half* __restrict__ X, const __half* __restrict__ Wg,
    const float* __restrict__ bias, __half* __restrict__ H)
{
    __shared__ __align__(16) __half As[64 * KVS];
    __shared__ __align__(16) __half Bs[64 * KVS];
    __shared__ float T[64 * 68];
    __shared__ float bss[64];
    int tid = threadIdx.x, w = tid >> 5, lane = tid & 31;
    int wm = w >> 1, wn = w & 1;
    int g = lane >> 2, r = lane & 3;
    int l0 = blockIdx.x * 64;
    int mb = blockIdx.y;
    int b  = blockIdx.z;

    if (tid < 64) bss[tid] = bias[mb * 64 + tid];
    for (int e = tid; e < 512; e += 256) {
        int row = e >> 3, kg = e & 7;
        *(uint4*)&As[row * KVS + kg * 8] =
            *(const uint4*)&Wg[(size_t)(mb * 64 + row) * 64 + kg * 8];
        *(uint4*)&Bs[row * KVS + kg * 8] =
            *(const uint4*)&X[((size_t)b * Lseq + l0 + row) * 64 + kg * 8];
    }
    __syncthreads();

    uint32_t ab = smem_u32(As) + (((wm * 16 + (lane & 15)) * KVS + ((lane >> 4) << 3)) * 2);
    uint32_t bb2 = smem_u32(Bs) + (((wn * 32 + (((lane >> 4) & 1) << 3) + (lane & 7)) * KVS +
                                    (((lane >> 3) & 1) << 3)) * 2);
    float acc[16];
#pragma unroll
    for (int i = 0; i < 16; i++) acc[i] = 0.f;
#pragma unroll
    for (int kc = 0; kc < 4; kc++) {
        uint32_t af0, af1, af2, af3;
        ldsm4(af0, af1, af2, af3, ab + kc * 32);
        uint32_t af[4] = {af0, af1, af2, af3};
        uint32_t b0, b1, b2, b3;
        ldsm4(b0, b1, b2, b3, bb2 + kc * 32);
        mma_f16(acc + 0, af, b0, b1);
        mma_f16(acc + 4, af, b2, b3);
        ldsm4(b0, b1, b2, b3, bb2 + 16 * KVS * 2 + kc * 32);
        mma_f16(acc + 8,  af, b0, b1);
        mma_f16(acc + 12, af, b2, b3);
    }
    __syncthreads();
    {
        float bv0 = bss[wm * 16 + g], bv1 = bss[wm * 16 + g + 8];
#pragma unroll
        for (int p = 0; p < 2; p++)
#pragma unroll
            for (int blk = 0; blk < 2; blk++) {
                int lb = wn * 32 + p * 16 + blk * 8 + 2 * r;
                int i = (p * 2 + blk) * 4;
                *(float2*)&T[(wm * 16 + g) * 68 + lb]     = make_float2(acc[i] + bv0, acc[i + 1] + bv0);
                *(float2*)&T[(wm * 16 + g + 8) * 68 + lb] = make_float2(acc[i + 2] + bv1, acc[i + 3] + bv1);
            }
    }
    __syncthreads();
    {
        int l = tid >> 2, cs = (tid & 3) * 16;
        __half* hp = H + ((size_t)b * Lseq + l0 + l) * 256 + mb * 64 + cs;
#pragma unroll
        for (int c = 0; c < 16; c += 2) {
            float v0 = fmaxf(T[(cs + c) * 68 + l], 0.f);
            float v1 = fmaxf(T[(cs + c + 1) * 68 + l], 0.f);
            *(uint32_t*)(hp + c) = hpack(v0, v1);
        }
    }
}

// ---------------- launch ----------------
extern "C" void kernel_launch(void* const* d_in, const int* in_sizes, int n_in,
                              void* d_out, int out_size)
{
    const float* q       = (const float*)d_in[0];
    const float* wq_pw   = (const float*)d_in[1];
    const float* wq_gate = (const float*)d_in[2];
    const float* wq_dw3  = (const float*)d_in[3];
    const float* wq_dw15 = (const float*)d_in[4];
    const float* wk_pw   = (const float*)d_in[5];
    const float* wk_gate = (const float*)d_in[6];
    const float* wk_dw3  = (const float*)d_in[7];
    const float* wk_dw15 = (const float*)d_in[8];
    const float* wv_pw   = (const float*)d_in[9];
    const float* wv_gate = (const float*)d_in[10];
    const float* wv_dw3  = (const float*)d_in[11];
    const float* wv_dw15 = (const float*)d_in[12];
    const float* w_unify = (const float*)d_in[13];
    const float* b_unify = (const float*)d_in[14];
    const float* ln1_g   = (const float*)d_in[15];
    const float* ln1_b   = (const float*)d_in[16];
    const float* ln2_g   = (const float*)d_in[17];
    const float* ln2_b   = (const float*)d_in[18];
    const float* ffn_w1  = (const float*)d_in[19];
    const float* ffn_b1  = (const float*)d_in[20];
    const float* ffn_w2  = (const float*)d_in[21];
    const float* ffn_b2  = (const float*)d_in[22];
    float* out = (float*)d_out;

    void *pPW, *pWF, *pqT, *pQ, *pK, *pV, *pATT, *pY, *pYh, *pH, *pWu, *pW1, *pW2;
    cudaGetSymbolAddress(&pPW, g_PW);
    cudaGetSymbolAddress(&pWF, g_WF);
    cudaGetSymbolAddress(&pqT, g_qT);
    cudaGetSymbolAddress(&pQ, g_Q);
    cudaGetSymbolAddress(&pK, g_K);
    cudaGetSymbolAddress(&pV, g_V);
    cudaGetSymbolAddress(&pATT, g_ATT);
    cudaGetSymbolAddress(&pY, g_Y);
    cudaGetSymbolAddress(&pYh, g_Yh);
    cudaGetSymbolAddress(&pH, g_H);
    cudaGetSymbolAddress(&pWu, g_Wu);
    cudaGetSymbolAddress(&pW1, g_W1);
    cudaGetSymbolAddress(&pW2, g_W2);

    cudaFuncSetAttribute(qkv_mma, cudaFuncAttributeMaxDynamicSharedMemorySize, 40960);

    combine_kernel<<<6, 256>>>(
        wq_pw, wq_gate, wq_dw3, wq_dw15,
        wk_pw, wk_gate, wk_dw3, wk_dw15,
        wv_pw, wv_gate, wv_dw3, wv_dw15,
        (float*)pPW, (float*)pWF);

    convw_kernel<<<256, 256>>>(w_unify, ffn_w1, ffn_w2);

    transpose_kernel<<<dim3(32, 16), 256>>>(q, (__half*)pqT);

    qkv_mma<<<dim3(8, 24, 16), 256, 40960>>>(
        (const __half*)pqT, (const float*)pPW, (const float*)pWF,
        (__half*)pQ, (__half*)pK, (__half*)pV);

    attn_f16<<<dim3(8, 128), 256>>>(
        (const __half*)pQ, (const __half*)pK, (const __half*)pV, (__half*)pATT);

    gemm_ln_kernel<<<dim3(16, 16), 256>>>(
        (const __half*)pATT, (const __half*)pWu,
        b_unify, q, ln1_g, ln1_b,
        (float*)pY, (__half*)pYh, 512);

    ffn1_mma<<<dim3(16, 4, 16), 256>>>(
        (const __half*)pYh, (const __half*)pW1,
        ffn_b1, (__half*)pH);

    gemm_ln_kernel<<<dim3(16, 16), 256>>>(
        (const __half*)pH, (const __half*)pW2,
        ffn_b2, (const float*)pY, ln2_g, ln2_b,
        out, (__half*)nullptr, 256);
}

// round 17
// speedup vs baseline: 2.4064x; 1.6392x over previous
#include <cuda_runtime.h>
#include <cuda_fp16.h>
#include <math.h>
#include <stdint.h>

#define Bsz  16
#define Cdim 64
#define Lseq 1024
#define Hn   8
#define HC   512
#define NH   128   // B*H batch-heads

// ---------------- scratch (static device memory; no allocations) ----------------
__device__ float g_PW[1536 * 64];
__device__ float g_WF[1536 * 15];
__device__ __half g_qT[Bsz * Lseq * Cdim];     // input transposed (b, l, c) fp16
__device__ __half g_Q[NH * Lseq * Cdim];       // (n, l, c) fp16, pre-scaled x0.125
__device__ __half g_K[NH * Lseq * Cdim];       // (n, l, c) fp16
__device__ __half g_V[NH * Cdim * Lseq];       // (n, c, l) fp16
__device__ __half g_ATT[Bsz * Lseq * HC];      // (b, l, hc) fp16
__device__ float g_Y[Bsz * Cdim * Lseq];       // LN1 out fp32 (b, c, l)
__device__ __half g_Yh[Bsz * Lseq * Cdim];     // LN1 out fp16 (b, l, c)
__device__ __half g_H[Bsz * Lseq * 256];       // FFN hidden fp16 (b, l, 256)
__device__ __half g_Wu[64 * 512];
__device__ __half g_W1[256 * 64];
__device__ __half g_W2[64 * 256];

__device__ __forceinline__ uint32_t hpack(float lo, float hi) {
    __half2 h = __floats2half2_rn(lo, hi);
    return *reinterpret_cast<uint32_t*>(&h);
}
__device__ __forceinline__ uint32_t smem_u32(const void* p) {
    uint32_t a;
    asm("{ .reg .u64 t; cvta.to.shared.u64 t, %1; cvt.u32.u64 %0, t; }" : "=r"(a) : "l"(p));
    return a;
}
__device__ __forceinline__ void mma_f16(float* c, const uint32_t* a, uint32_t b0, uint32_t b1) {
    asm volatile(
        "mma.sync.aligned.m16n8k16.row.col.f32.f16.f16.f32 "
        "{%0,%1,%2,%3}, {%4,%5,%6,%7}, {%8,%9}, {%0,%1,%2,%3};"
        : "+f"(c[0]), "+f"(c[1]), "+f"(c[2]), "+f"(c[3])
        : "r"(a[0]), "r"(a[1]), "r"(a[2]), "r"(a[3]), "r"(b0), "r"(b1));
}
__device__ __forceinline__ void ldsm4(uint32_t& r0, uint32_t& r1, uint32_t& r2, uint32_t& r3,
                                      uint32_t addr) {
    asm volatile("ldmatrix.sync.aligned.m8n8.x4.shared.b16 {%0,%1,%2,%3}, [%4];"
                 : "=r"(r0), "=r"(r1), "=r"(r2), "=r"(r3) : "r"(addr));
}
#define CP16(dst, src) \
    asm volatile("cp.async.cg.shared.global [%0], [%1], 16;" :: "r"(dst), "l"(src))
#define CP_COMMIT() asm volatile("cp.async.commit_group;" ::: "memory")
#define CP_WAIT1()  asm volatile("cp.async.wait_group 1;" ::: "memory")

// ---------------- K0: fold gate softmax into combined conv weights ----------------
__global__ void combine_kernel(
    const float* __restrict__ pw0, const float* __restrict__ gt0,
    const float* __restrict__ d3_0, const float* __restrict__ d15_0,
    const float* __restrict__ pw1, const float* __restrict__ gt1,
    const float* __restrict__ d3_1, const float* __restrict__ d15_1,
    const float* __restrict__ pw2, const float* __restrict__ gt2,
    const float* __restrict__ d3_2, const float* __restrict__ d15_2,
    float* __restrict__ PW, float* __restrict__ WF)
{
    int o = blockIdx.x * 256 + threadIdx.x;
    if (o >= 1536) return;
    int s = o >> 9, lc = o & 511;
    const float *pw, *gt, *d3, *d15;
    if (s == 0)      { pw = pw0; gt = gt0; d3 = d3_0; d15 = d15_0; }
    else if (s == 1) { pw = pw1; gt = gt1; d3 = d3_1; d15 = d15_1; }
    else             { pw = pw2; gt = gt2; d3 = d3_2; d15 = d15_2; }
    float a = gt[0], b = gt[1];
    float mx = fmaxf(a, b);
    float e0 = expf(a - mx), e1 = expf(b - mx);
    float inv = 1.0f / (e0 + e1);
    float ga = e0 * inv, gb = e1 * inv;
    for (int c = 0; c < 64; c++) PW[(size_t)o * 64 + c] = pw[(size_t)lc * 64 + c];
    for (int t = 0; t < 15; t++) {
        float w = gb * d15[lc * 15 + t];
        if (t >= 6 && t < 9) w += ga * d3[lc * 3 + (t - 6)];
        WF[o * 15 + t] = w;
    }
}

// ---------------- K0b: weights -> fp16 ----------------
__global__ void convw_kernel(const float* __restrict__ wu, const float* __restrict__ w1,
                             const float* __restrict__ w2)
{
    int i = blockIdx.x * 256 + threadIdx.x;
    if (i < 32768)       g_Wu[i] = __float2half_rn(wu[i]);
    else if (i < 49152)  g_W1[i - 32768] = __float2half_rn(w1[i - 32768]);
    else if (i < 65536)  g_W2[i - 49152] = __float2half_rn(w2[i - 49152]);
}

// ---------------- K0c: transpose q (b,c,l) f32 -> (b,l,c) fp16 ----------------
__global__ __launch_bounds__(256) void transpose_kernel(
    const float* __restrict__ q, __half* __restrict__ qT)
{
    __shared__ float tile[64][33];
    int b = blockIdx.y, l0 = blockIdx.x * 32;
    int t = threadIdx.x;
    int c = t >> 2, lo4 = (t & 3) * 8;
    float4 v0 = *(const float4*)&q[((size_t)b * 64 + c) * Lseq + l0 + lo4];
    float4 v1 = *(const float4*)&q[((size_t)b * 64 + c) * Lseq + l0 + lo4 + 4];
    tile[c][lo4 + 0] = v0.x; tile[c][lo4 + 1] = v0.y;
    tile[c][lo4 + 2] = v0.z; tile[c][lo4 + 3] = v0.w;
    tile[c][lo4 + 4] = v1.x; tile[c][lo4 + 5] = v1.y;
    tile[c][lo4 + 6] = v1.z; tile[c][lo4 + 7] = v1.w;
    __syncthreads();
    int l = t >> 3, c0 = (t & 7) * 8;
    uint32_t hp[4];
#pragma unroll
    for (int j = 0; j < 4; j++)
        hp[j] = hpack(tile[c0 + 2 * j][l], tile[c0 + 2 * j + 1][l]);
    *(uint4*)&qT[((size_t)b * Lseq + l0 + l) * 64 + c0] = *(uint4*)hp;
}

// ---------------- K1: qkv via fp16 mma pointwise + fp32 depthwise conv ----------------
// grid (8 Ltiles of 128, 24 o-blocks of 64, 16 b); 256 threads. dyn smem 41984.
#define BST 72           // fp16 row stride in staging tiles
#define MIDS 164         // fp32 mid row stride (164 % 32 = 4 -> conflict-free across channels)
__global__ __launch_bounds__(256) void qkv_mma(
    const __half* __restrict__ qT,
    const float* __restrict__ PW, const float* __restrict__ WF,
    __half* __restrict__ Qp, __half* __restrict__ Kp, __half* __restrict__ Vp)
{
    extern __shared__ __align__(16) char SM[];
    __half* As = (__half*)SM;               // [64][72]
    __half* Bs = (__half*)(SM + 9216);      // [160][72]
    float*  mid = (float*)SM;               // [64][164] (reused after mma)
    __shared__ float swf[64 * 16];
    int tid = threadIdx.x, w = tid >> 5, lane = tid & 31;
    int wm = w >> 1, wn = w & 1;
    int g = lane >> 2, r = lane & 3;
    int l0 = blockIdx.x * 128;
    int o0 = blockIdx.y * 64;
    int b  = blockIdx.z;

    // stage A (weights fp32 -> fp16), conv weights
    for (int e = tid; e < 4096; e += 256) {
        int o = e >> 6, c = e & 63;
        As[o * BST + c] = __float2half_rn(PW[(size_t)(o0 + o) * 64 + c]);
    }
    for (int e = tid; e < 64 * 15; e += 256) {
        int o = e / 15, t = e - o * 15;
        swf[o * 16 + t] = WF[(size_t)(o0 + o) * 15 + t];
    }
    // stage B: rows j=0..159 <-> position l0-7+j (zero pad OOB / j>=144)
    const __half* qTb = qT + (size_t)b * Lseq * 64;
#pragma unroll
    for (int k = 0; k < 5; k++) {
        int gi = tid + k * 256;
        int row = gi >> 3, gr = gi & 7;
        int l = l0 - 7 + row;
        uint4 v = make_uint4(0, 0, 0, 0);
        if (row < 144 && l >= 0 && l < Lseq)
            v = *(const uint4*)&qTb[(size_t)l * 64 + gr * 8];
        *(uint4*)&Bs[row * BST + gr * 8] = v;
    }
    __syncthreads();

    uint32_t asb = smem_u32(As), bsb = smem_u32(Bs);
    uint32_t a_off = asb + (((wm * 16 + (lane & 15)) * BST + ((lane >> 4) << 3)) * 2);
    uint32_t b_off = bsb + (((wn * 80 + (((lane >> 4) & 1) << 3) + (lane & 7)) * BST +
                             (((lane >> 3) & 1) << 3)) * 2);
    float acc[40];
#pragma unroll
    for (int i = 0; i < 40; i++) acc[i] = 0.f;
#pragma unroll
    for (int kc = 0; kc < 4; kc++) {
        uint32_t af0, af1, af2, af3;
        ldsm4(af0, af1, af2, af3, a_off + kc * 32);
        uint32_t af[4] = {af0, af1, af2, af3};
#pragma unroll
        for (int nb2 = 0; nb2 < 5; nb2++) {
            uint32_t b0, b1, b2, b3;
            ldsm4(b0, b1, b2, b3, b_off + nb2 * (16 * BST * 2) + kc * 32);
            mma_f16(acc + (nb2 * 2 + 0) * 4, af, b0, b1);
            mma_f16(acc + (nb2 * 2 + 1) * 4, af, b2, b3);
        }
    }
    __syncthreads();   // staging dead; write mid

    {
        int ro0 = wm * 16 + g, ro1 = ro0 + 8;
#pragma unroll
        for (int nb2 = 0; nb2 < 5; nb2++)
#pragma unroll
            for (int blk = 0; blk < 2; blk++) {
                int col = wn * 80 + nb2 * 16 + blk * 8 + 2 * r;
                int i = (nb2 * 2 + blk) * 4;
                *(float2*)&mid[ro0 * MIDS + col] = make_float2(acc[i], acc[i + 1]);
                *(float2*)&mid[ro1 * MIDS + col] = make_float2(acc[i + 2], acc[i + 3]);
            }
    }
    __syncthreads();

    // depthwise conv15 via register sliding window:
    // thread = (channel o = tid&63, position block ib); 2 blocks of 16 positions each.
    int s = o0 >> 9;
    float scale = (s == 0) ? 0.125f : 1.0f;
    int ch0 = o0 & 511, head = ch0 >> 6;
    size_t n = (size_t)b * 8 + head;
    int o = tid & 63;
    float wr[15];
#pragma unroll
    for (int t = 0; t < 15; t++) wr[t] = swf[o * 16 + t];

#pragma unroll
    for (int u = 0; u < 2; u++) {
        int ib = (tid >> 6) + u * 4;    // 0..7
        int i0 = ib * 16;
        const float* mrow = mid + o * MIDS + i0;
        float win[32];
#pragma unroll
        for (int j = 0; j < 8; j++)
            *(float4*)(win + 4 * j) = *(const float4*)(mrow + 4 * j);
        __half hv[16];
#pragma unroll
        for (int i = 0; i < 16; i++) {
            float a2 = 0.f;
#pragma unroll
            for (int t = 0; t < 15; t++) a2 += wr[t] * win[i + t];
            hv[i] = __float2half_rn(a2 * scale);
        }
        if (s == 2) {
            // (n, c, l): 16 consecutive l -> 2 vector stores
            __half* vp = Vp + (n * 64 + o) * Lseq + l0 + i0;
            *(uint4*)vp = *(uint4*)hv;
            *(uint4*)(vp + 8) = *(uint4*)(hv + 8);
        } else {
            __half* base = (s == 0) ? Qp : Kp;
#pragma unroll
            for (int i = 0; i < 16; i++)
                base[(n * Lseq + l0 + i0 + i) * 64 + o] = hv[i];
        }
    }
}

// ---------------- K2: flash attention fp16 ----------------
#define KVS 72
#define BUFE (64 * KVS)
__global__ __launch_bounds__(256, 2) void attn_f16(
    const __half* __restrict__ Qt, const __half* __restrict__ Kt,
    const __half* __restrict__ Vg, __half* __restrict__ att)
{
    __shared__ __half Ks[2][BUFE];
    __shared__ __half Vs[2][BUFE];
    int tid = threadIdx.x, w = tid >> 5, lane = tid & 31;
    int g = lane >> 2, r = lane & 3;
    int n = blockIdx.y, q0 = blockIdx.x * 128;

    const __half* Qb = Qt + (size_t)n * (Lseq * 64) + (size_t)(q0 + w * 16) * 64;
    const __half* Kb = Kt + (size_t)n * (Lseq * 64);
    const __half* Vb = Vg + (size_t)n * (64 * Lseq);

    int kr0 = tid >> 3, kg0 = tid & 7;
    int kr1 = (tid + 256) >> 3, kg1 = (tid + 256) & 7;
    uint32_t ks_base = smem_u32(&Ks[0][0]);
    uint32_t vs_base = smem_u32(&Vs[0][0]);
    uint32_t kd0 = ks_base + (kr0 * KVS + kg0 * 8) * 2;
    uint32_t kd1 = ks_base + (kr1 * KVS + kg1 * 8) * 2;
    uint32_t vd0 = vs_base + (kr0 * KVS + kg0 * 8) * 2;
    uint32_t vd1 = vs_base + (kr1 * KVS + kg1 * 8) * 2;

    int sel = lane >> 3, lrow = lane & 7;
    int mrow = ((sel >> 1) << 3) + lrow;
    int mcol = (sel & 1) << 3;
    uint32_t kls = ks_base + (mrow * KVS + mcol) * 2;
    uint32_t vls = vs_base + (mrow * KVS + mcol) * 2;

    uint32_t qf[16];
#pragma unroll
    for (int kc = 0; kc < 4; kc++) {
        qf[kc * 4 + 0] = *(const uint32_t*)(Qb + (size_t)g * 64 + kc * 16 + 2 * r);
        qf[kc * 4 + 1] = *(const uint32_t*)(Qb + (size_t)(g + 8) * 64 + kc * 16 + 2 * r);
        qf[kc * 4 + 2] = *(const uint32_t*)(Qb + (size_t)g * 64 + kc * 16 + 2 * r + 8);
        qf[kc * 4 + 3] = *(const uint32_t*)(Qb + (size_t)(g + 8) * 64 + kc * 16 + 2 * r + 8);
    }

#pragma unroll
    for (int t = 0; t < 2; t++) {
        int k0 = t * 64;
        uint32_t bo = t * BUFE * 2;
        CP16(kd0 + bo, Kb + (size_t)(k0 + kr0) * 64 + kg0 * 8);
        CP16(kd1 + bo, Kb + (size_t)(k0 + kr1) * 64 + kg1 * 8);
        CP16(vd0 + bo, Vb + (size_t)kr0 * Lseq + k0 + kg0 * 8);
        CP16(vd1 + bo, Vb + (size_t)kr1 * Lseq + k0 + kg1 * 8);
        CP_COMMIT();
    }

    float oacc[32];
#pragma unroll
    for (int i = 0; i < 32; i++) oacc[i] = 0.f;
    float m0 = -INFINITY, m1 = -INFINITY, l0 = 0.f, l1 = 0.f;

    for (int kt = 0; kt < 16; kt++) {
        CP_WAIT1();
        __syncthreads();
        uint32_t bo = (kt & 1) * BUFE * 2;

        float sacc[32];
#pragma unroll
        for (int i = 0; i < 32; i++) sacc[i] = 0.f;
#pragma unroll
        for (int kc = 0; kc < 4; kc++) {
#pragma unroll
            for (int nb2 = 0; nb2 < 4; nb2++) {
                uint32_t b0, b1, b2, b3;
                ldsm4(b0, b1, b2, b3, kls + bo + nb2 * (16 * KVS * 2) + kc * 32);
                mma_f16(sacc + (2 * nb2) * 4,     qf + kc * 4, b0, b1);
                mma_f16(sacc + (2 * nb2 + 1) * 4, qf + kc * 4, b2, b3);
            }
        }

        float tm0 = -INFINITY, tm1 = -INFINITY;
#pragma unroll
        for (int nb = 0; nb < 8; nb++) {
            tm0 = fmaxf(tm0, fmaxf(sacc[nb * 4 + 0], sacc[nb * 4 + 1]));
            tm1 = fmaxf(tm1, fmaxf(sacc[nb * 4 + 2], sacc[nb * 4 + 3]));
        }
        tm0 = fmaxf(tm0, __shfl_xor_sync(0xffffffffu, tm0, 1));
        tm0 = fmaxf(tm0, __shfl_xor_sync(0xffffffffu, tm0, 2));
        tm1 = fmaxf(tm1, __shfl_xor_sync(0xffffffffu, tm1, 1));
        tm1 = fmaxf(tm1, __shfl_xor_sync(0xffffffffu, tm1, 2));
        float mn0 = fmaxf(m0, tm0), mn1 = fmaxf(m1, tm1);
        float al0 = __expf(m0 - mn0), al1 = __expf(m1 - mn1);
        m0 = mn0; m1 = mn1;
        float s0 = 0.f, s1 = 0.f;
        uint32_t plo[8], phi[8];
#pragma unroll
        for (int nb = 0; nb < 8; nb++) {
            float p0 = __expf(sacc[nb * 4 + 0] - mn0);
            float p1 = __expf(sacc[nb * 4 + 1] - mn0);
            float p2 = __expf(sacc[nb * 4 + 2] - mn1);
            float p3 = __expf(sacc[nb * 4 + 3] - mn1);
            s0 += p0 + p1; s1 += p2 + p3;
            plo[nb] = hpack(p0, p1);
            phi[nb] = hpack(p2, p3);
        }
        s0 += __shfl_xor_sync(0xffffffffu, s0, 1);
        s0 += __shfl_xor_sync(0xffffffffu, s0, 2);
        s1 += __shfl_xor_sync(0xffffffffu, s1, 1);
        s1 += __shfl_xor_sync(0xffffffffu, s1, 2);
        l0 = l0 * al0 + s0;
        l1 = l1 * al1 + s1;
#pragma unroll
        for (int nb = 0; nb < 8; nb++) {
            oacc[nb * 4 + 0] *= al0; oacc[nb * 4 + 1] *= al0;
            oacc[nb * 4 + 2] *= al1; oacc[nb * 4 + 3] *= al1;
        }

#pragma unroll
        for (int kc = 0; kc < 4; kc++) {
            uint32_t pa[4] = {plo[2 * kc], phi[2 * kc], plo[2 * kc + 1], phi[2 * kc + 1]};
#pragma unroll
            for (int nb2 = 0; nb2 < 4; nb2++) {
                uint32_t b0, b1, b2, b3;
                ldsm4(b0, b1, b2, b3, vls + bo + nb2 * (16 * KVS * 2) + kc * 32);
                mma_f16(oacc + (2 * nb2) * 4,     pa, b0, b1);
                mma_f16(oacc + (2 * nb2 + 1) * 4, pa, b2, b3);
            }
        }

        __syncthreads();
        if (kt < 14) {
            int k0 = (kt + 2) * 64;
            uint32_t nb_ = (kt & 1) * BUFE * 2;
            CP16(kd0 + nb_, Kb + (size_t)(k0 + kr0) * 64 + kg0 * 8);
            CP16(kd1 + nb_, Kb + (size_t)(k0 + kr1) * 64 + kg1 * 8);
            CP16(vd0 + nb_, Vb + (size_t)kr0 * Lseq + k0 + kg0 * 8);
            CP16(vd1 + nb_, Vb + (size_t)kr1 * Lseq + k0 + kg1 * 8);
        }
        CP_COMMIT();
    }

    float inv0 = 1.0f / l0, inv1 = 1.0f / l1;
    int bb = n >> 3, head = n & 7;
    int qg0 = q0 + w * 16 + g, qg1 = qg0 + 8;
#pragma unroll
    for (int nb = 0; nb < 8; nb++) {
        int c = head * 64 + nb * 8 + 2 * r;
        *(uint32_t*)&att[((size_t)bb * Lseq + qg0) * 512 + c] =
            hpack(oacc[nb * 4 + 0] * inv0, oacc[nb * 4 + 1] * inv0);
        *(uint32_t*)&att[((size_t)bb * Lseq + qg1) * 512 + c] =
            hpack(oacc[nb * 4 + 2] * inv1, oacc[nb * 4 + 3] * inv1);
    }
}

// ---------------- K3/K5: fp16 mma GEMM (64 x Kdim) + bias + residual + channel LN ----------------
__global__ __launch_bounds__(256) void gemm_ln_kernel(
    const __half* __restrict__ X,    // (b, 1024, Kdim) fp16
    const __half* __restrict__ Wg,   // (64, Kdim) fp16
    const float* __restrict__ bias, const float* __restrict__ res,
    const float* __restrict__ gam, const float* __restrict__ bet,
    float* __restrict__ outF,
    __half* __restrict__ outH,
    int Kdim)
{
    __shared__ __align__(16) char SM[36864];
    __shared__ float ps1[4 * 64], ps2[4 * 64], mu_s[64], iv_s[64];
    __shared__ float gs[64], bts[64], bss[64];
    int tid = threadIdx.x, w = tid >> 5, lane = tid & 31;
    int wm = w >> 1, wn = w & 1;
    int g = lane >> 2, r = lane & 3;
    int l0 = blockIdx.x * 64;
    int b  = blockIdx.y;
    int nch = Kdim >> 6;

    if (tid < 64) { gs[tid] = gam[tid]; bts[tid] = bet[tid]; bss[tid] = bias[tid]; }

    uint32_t asb = smem_u32(SM);
    uint32_t bsb = asb + 18432;
    uint32_t a_off = (uint32_t)(((wm * 16 + (lane & 15)) * KVS + ((lane >> 4) << 3)) * 2);
    uint32_t b_off = (uint32_t)(((wn * 32 + (((lane >> 4) & 1) << 3) + (lane & 7)) * KVS +
                                 (((lane >> 3) & 1) << 3)) * 2);
    int sr0 = tid >> 3, sg0 = tid & 7;
    int sr1 = (tid + 256) >> 3, sg1 = (tid + 256) & 7;
    uint32_t ad0 = asb + (sr0 * KVS + sg0 * 8) * 2;
    uint32_t ad1 = asb + (sr1 * KVS + sg1 * 8) * 2;
    uint32_t bd0 = bsb + (sr0 * KVS + sg0 * 8) * 2;
    uint32_t bd1 = bsb + (sr1 * KVS + sg1 * 8) * 2;
    const __half* Xb = X + (size_t)b * Lseq * Kdim;

#pragma unroll
    for (int t = 0; t < 2; t++) {
        int cb = t * 64;
        uint32_t bo = t * 9216;
        CP16(ad0 + bo, Wg + (size_t)sr0 * Kdim + cb + sg0 * 8);
        CP16(ad1 + bo, Wg + (size_t)sr1 * Kdim + cb + sg1 * 8);
        CP16(bd0 + bo, Xb + (size_t)(l0 + sr0) * Kdim + cb + sg0 * 8);
        CP16(bd1 + bo, Xb + (size_t)(l0 + sr1) * Kdim + cb + sg1 * 8);
        CP_COMMIT();
    }

    float acc[16];
#pragma unroll
    for (int i = 0; i < 16; i++) acc[i] = 0.f;

    for (int c = 0; c < nch; c++) {
        CP_WAIT1();
        __syncthreads();
        uint32_t bo = (c & 1) * 9216;
        uint32_t ab = asb + bo + a_off;
        uint32_t bb2 = bsb + bo + b_off;
#pragma unroll
        for (int kc = 0; kc < 4; kc++) {
            uint32_t af0, af1, af2, af3;
            ldsm4(af0, af1, af2, af3, ab + kc * 32);
            uint32_t af[4] = {af0, af1, af2, af3};
            uint32_t b0, b1, b2, b3;
            ldsm4(b0, b1, b2, b3, bb2 + kc * 32);
            mma_f16(acc + 0, af, b0, b1);
            mma_f16(acc + 4, af, b2, b3);
            ldsm4(b0, b1, b2, b3, bb2 + 16 * KVS * 2 + kc * 32);
            mma_f16(acc + 8,  af, b0, b1);
            mma_f16(acc + 12, af, b2, b3);
        }
        __syncthreads();
        if (c + 2 < nch) {
            int cb = (c + 2) * 64;
            uint32_t nb_ = (c & 1) * 9216;
            CP16(ad0 + nb_, Wg + (size_t)sr0 * Kdim + cb + sg0 * 8);
            CP16(ad1 + nb_, Wg + (size_t)sr1 * Kdim + cb + sg1 * 8);
            CP16(bd0 + nb_, Xb + (size_t)(l0 + sr0) * Kdim + cb + sg0 * 8);
            CP16(bd1 + nb_, Xb + (size_t)(l0 + sr1) * Kdim + cb + sg1 * 8);
        }
        CP_COMMIT();
    }
    __syncthreads();

    float* T = (float*)SM;
    float* R = (float*)(SM + 18432);
    {
        float bv0 = bss[wm * 16 + g], bv1 = bss[wm * 16 + g + 8];
#pragma unroll
        for (int p = 0; p < 2; p++)
#pragma unroll
            for (int blk = 0; blk < 2; blk++) {
                int lb = wn * 32 + p * 16 + blk * 8 + 2 * r;
                int i = (p * 2 + blk) * 4;
                *(float2*)&T[(wm * 16 + g) * 68 + lb]     = make_float2(acc[i] + bv0, acc[i + 1] + bv0);
                *(float2*)&T[(wm * 16 + g + 8) * 68 + lb] = make_float2(acc[i + 2] + bv1, acc[i + 3] + bv1);
            }
    }
    for (int e = tid; e < 1024; e += 256) {
        int row = e >> 4, sg = e & 15;
        *(float4*)&R[row * 68 + sg * 4] =
            *(const float4*)&res[((size_t)b * 64 + row) * Lseq + l0 + sg * 4];
    }
    __syncthreads();

    {
        int l = tid & 63, p = tid >> 6;
        float s1 = 0.f, s2 = 0.f;
#pragma unroll
        for (int ch = p * 16; ch < p * 16 + 16; ch++) {
            float v = T[ch * 68 + l] + R[ch * 68 + l];
            s1 += v; s2 += v * v;
        }
        ps1[p * 64 + l] = s1; ps2[p * 64 + l] = s2;
    }
    __syncthreads();
    if (tid < 64) {
        float s1 = ps1[tid] + ps1[64 + tid] + ps1[128 + tid] + ps1[192 + tid];
        float s2 = ps2[tid] + ps2[64 + tid] + ps2[128 + tid] + ps2[192 + tid];
        float mu = s1 * (1.0f / 64.0f);
        float var = s2 * (1.0f / 64.0f) - mu * mu;
        mu_s[tid] = mu;
        iv_s[tid] = rsqrtf(var + 1e-5f);
    }
    __syncthreads();

    {
        int ch = tid >> 2, ls = (tid & 3) * 16;
        float gv = gs[ch], bv = bts[ch];
        float* op = outF + ((size_t)b * 64 + ch) * Lseq + l0 + ls;
#pragma unroll
        for (int j = 0; j < 16; j += 4) {
            float4 ov;
            float* tp = &T[ch * 68 + ls + j];
            float* rp = &R[ch * 68 + ls + j];
            ov.x = (tp[0] + rp[0] - mu_s[ls + j + 0]) * iv_s[ls + j + 0] * gv + bv;
            ov.y = (tp[1] + rp[1] - mu_s[ls + j + 1]) * iv_s[ls + j + 1] * gv + bv;
            ov.z = (tp[2] + rp[2] - mu_s[ls + j + 2]) * iv_s[ls + j + 2] * gv + bv;
            ov.w = (tp[3] + rp[3] - mu_s[ls + j + 3]) * iv_s[ls + j + 3] * gv + bv;
            *(float4*)(op + j) = ov;
        }
    }
    if (outH) {
        int l = tid >> 2, cs = (tid & 3) * 16;
        float mu = mu_s[l], iv = iv_s[l];
        __half* hp = outH + ((size_t)b * Lseq + l0 + l) * 64 + cs;
#pragma unroll
        for (int c = 0; c < 16; c += 2) {
            float v0 = (T[(cs + c) * 68 + l] + R[(cs + c) * 68 + l] - mu) * iv * gs[cs + c] + bts[cs + c];
            float v1 = (T[(cs + c + 1) * 68 + l] + R[(cs + c + 1) * 68 + l] - mu) * iv * gs[cs + c + 1] + bts[cs + c + 1];
            *(uint32_t*)(hp + c) = hpack(v0, v1);
        }
    }
}

// ---------------- K4: FFN up-projection fp16 mma + ReLU ----------------
__global__ __launch_bounds__(256) void ffn1_mma(
    const __half* __restrict__ X, const __half* __restrict__ Wg,
    const float* __restrict__ bias, __half* __restrict__ H)
{
    __shared__ __align__(16) __half As[64 * KVS];
    __shared__ __align__(16) __half Bs[64 * KVS];
    __shared__ float T[64 * 68];
    __shared__ float bss[64];
    int tid = threadIdx.x, w = tid >> 5, lane = tid & 31;
    int wm = w >> 1, wn = w & 1;
    int g = lane >> 2, r = lane & 3;
    int l0 = blockIdx.x * 64;
    int mb = blockIdx.y;
    int b  = blockIdx.z;

    if (tid < 64) bss[tid] = bias[mb * 64 + tid];
    for (int e = tid; e < 512; e += 256) {
        int row = e >> 3, kg = e & 7;
        *(uint4*)&As[row * KVS + kg * 8] =
            *(const uint4*)&Wg[(size_t)(mb * 64 + row) * 64 + kg * 8];
        *(uint4*)&Bs[row * KVS + kg * 8] =
            *(const uint4*)&X[((size_t)b * Lseq + l0 + row) * 64 + kg * 8];
    }
    __syncthreads();

    uint32_t ab = smem_u32(As) + (((wm * 16 + (lane & 15)) * KVS + ((lane >> 4) << 3)) * 2);
    uint32_t bb2 = smem_u32(Bs) + (((wn * 32 + (((lane >> 4) & 1) << 3) + (lane & 7)) * KVS +
                                    (((lane >> 3) & 1) << 3)) * 2);
    float acc[16];
#pragma unroll
    for (int i = 0; i < 16; i++) acc[i] = 0.f;
#pragma unroll
    for (int kc = 0; kc < 4; kc++) {
        uint32_t af0, af1, af2, af3;
        ldsm4(af0, af1, af2, af3, ab + kc * 32);
        uint32_t af[4] = {af0, af1, af2, af3};
        uint32_t b0, b1, b2, b3;
        ldsm4(b0, b1, b2, b3, bb2 + kc * 32);
        mma_f16(acc + 0, af, b0, b1);
        mma_f16(acc + 4, af, b2, b3);
        ldsm4(b0, b1, b2, b3, bb2 + 16 * KVS * 2 + kc * 32);
        mma_f16(acc + 8,  af, b0, b1);
        mma_f16(acc + 12, af, b2, b3);
    }
    __syncthreads();
    {
        float bv0 = bss[wm * 16 + g], bv1 = bss[wm * 16 + g + 8];
#pragma unroll
        for (int p = 0; p < 2; p++)
#pragma unroll
            for (int blk = 0; blk < 2; blk++) {
                int lb = wn * 32 + p * 16 + blk * 8 + 2 * r;
                int i = (p * 2 + blk) * 4;
                *(float2*)&T[(wm * 16 + g) * 68 + lb]     = make_float2(acc[i] + bv0, acc[i + 1] + bv0);
                *(float2*)&T[(wm * 16 + g + 8) * 68 + lb] = make_float2(acc[i + 2] + bv1, acc[i + 3] + bv1);
            }
    }
    __syncthreads();
    {
        int l = tid >> 2, cs = (tid & 3) * 16;
        __half* hp = H + ((size_t)b * Lseq + l0 + l) * 256 + mb * 64 + cs;
#pragma unroll
        for (int c = 0; c < 16; c += 2) {
            float v0 = fmaxf(T[(cs + c) * 68 + l], 0.f);
            float v1 = fmaxf(T[(cs + c + 1) * 68 + l], 0.f);
            *(uint32_t*)(hp + c) = hpack(v0, v1);
        }
    }
}

// ---------------- launch ----------------
extern "C" void kernel_launch(void* const* d_in, const int* in_sizes, int n_in,
                              void* d_out, int out_size)
{
    const float* q       = (const float*)d_in[0];
    const float* wq_pw   = (const float*)d_in[1];
    const float* wq_gate = (const float*)d_in[2];
    const float* wq_dw3  = (const float*)d_in[3];
    const float* wq_dw15 = (const float*)d_in[4];
    const float* wk_pw   = (const float*)d_in[5];
    const float* wk_gate = (const float*)d_in[6];
    const float* wk_dw3  = (const float*)d_in[7];
    const float* wk_dw15 = (const float*)d_in[8];
    const float* wv_pw   = (const float*)d_in[9];
    const float* wv_gate = (const float*)d_in[10];
    const float* wv_dw3  = (const float*)d_in[11];
    const float* wv_dw15 = (const float*)d_in[12];
    const float* w_unify = (const float*)d_in[13];
    const float* b_unify = (const float*)d_in[14];
    const float* ln1_g   = (const float*)d_in[15];
    const float* ln1_b   = (const float*)d_in[16];
    const float* ln2_g   = (const float*)d_in[17];
    const float* ln2_b   = (const float*)d_in[18];
    const float* ffn_w1  = (const float*)d_in[19];
    const float* ffn_b1  = (const float*)d_in[20];
    const float* ffn_w2  = (const float*)d_in[21];
    const float* ffn_b2  = (const float*)d_in[22];
    float* out = (float*)d_out;

    void *pPW, *pWF, *pqT, *pQ, *pK, *pV, *pATT, *pY, *pYh, *pH, *pWu, *pW1, *pW2;
    cudaGetSymbolAddress(&pPW, g_PW);
    cudaGetSymbolAddress(&pWF, g_WF);
    cudaGetSymbolAddress(&pqT, g_qT);
    cudaGetSymbolAddress(&pQ, g_Q);
    cudaGetSymbolAddress(&pK, g_K);
    cudaGetSymbolAddress(&pV, g_V);
    cudaGetSymbolAddress(&pATT, g_ATT);
    cudaGetSymbolAddress(&pY, g_Y);
    cudaGetSymbolAddress(&pYh, g_Yh);
    cudaGetSymbolAddress(&pH, g_H);
    cudaGetSymbolAddress(&pWu, g_Wu);
    cudaGetSymbolAddress(&pW1, g_W1);
    cudaGetSymbolAddress(&pW2, g_W2);

    cudaFuncSetAttribute(qkv_mma, cudaFuncAttributeMaxDynamicSharedMemorySize, 41984);

    combine_kernel<<<6, 256>>>(
        wq_pw, wq_gate, wq_dw3, wq_dw15,
        wk_pw, wk_gate, wk_dw3, wk_dw15,
        wv_pw, wv_gate, wv_dw3, wv_dw15,
        (float*)pPW, (float*)pWF);

    convw_kernel<<<256, 256>>>(w_unify, ffn_w1, ffn_w2);

    transpose_kernel<<<dim3(32, 16), 256>>>(q, (__half*)pqT);

    qkv_mma<<<dim3(8, 24, 16), 256, 41984>>>(
        (const __half*)pqT, (const float*)pPW, (const float*)pWF,
        (__half*)pQ, (__half*)pK, (__half*)pV);

    attn_f16<<<dim3(8, 128), 256>>>(
        (const __half*)pQ, (const __half*)pK, (const __half*)pV, (__half*)pATT);

    gemm_ln_kernel<<<dim3(16, 16), 256>>>(
        (const __half*)pATT, (const __half*)pWu,
        b_unify, q, ln1_g, ln1_b,
        (float*)pY, (__half*)pYh, 512);

    ffn1_mma<<<dim3(16, 4, 16), 256>>>(
        (const __half*)pYh, (const __half*)pW1,
        ffn_b1, (__half*)pH);

    gemm_ln_kernel<<<dim3(16, 16), 256>>>(
        (const __half*)pH, (const __half*)pW2,
        ffn_b2, (const float*)pY, ln2_g, ln2_b,
        out, (__half*)nullptr, 256);
}